// round 1
// baseline (speedup 1.0000x reference)
#include <cuda_runtime.h>
#include <cuda_bf16.h>
#include <math.h>

#define NB    4
#define NOBJ  135
#define NFEAT 540
#define ZD    64
#define HID   512
#define NOUT  12288   // 3*64*64
#define IMGW  128
#define OBJW  64

// ---------------- scratch (device globals; no allocation allowed) ----------
__device__ int           g_order[NB][NFEAT];
__device__ float4        g_candf[NB][NFEAT];   // ax=2cx-1, ay=2cy-1, w, h (clamped)
__device__ int           g_candd[NB][NFEAT];   // distinct decode index 0..134
__device__ int           g_ncand[NB];
__device__ unsigned char g_need[NB][NOBJ];
__device__ int           g_rows[560];          // compacted needed rows (b*135+o)
__device__ int           g_nrows;
__device__ float         g_h[560][HID];        // hidden activations per compact slot
__device__ float         g_dec[NB*NOBJ][NOUT]; // decoded patches (by b*135+o)
__device__ int           g_winner[NB][IMGW][IMGW];

__device__ __forceinline__ int recon_idx(int j) {
    if (j < 400) return j >> 2;                   // 10x10 map, 4 boxes
    if (j < 500) return 100 + ((j - 400) >> 2);   // 5x5
    if (j < 536) return 125 + ((j - 500) >> 2);   // 3x3
    return 134;                                   // 1x1
}

// ---------------- K1: stable descending sort by depth + candidate compaction
__global__ void k_sort(const float* __restrict__ zdepth,
                       const float* __restrict__ zwhere,
                       const int*   __restrict__ zpres) {
    int b = blockIdx.x;
    __shared__ float sd[NFEAT];
    __shared__ int   sord[NFEAT];
    __shared__ int   swsum[17];
    int t = threadIdx.x;   // blockDim = 544 (17 full warps)

    if (t < NFEAT) sd[t] = zdepth[b * NOBJ + recon_idx(t)];
    if (t < NOBJ)  g_need[b][t] = 0;
    __syncthreads();

    if (t < NFEAT) {
        float dj = sd[t];
        int r = 0;
        for (int k = 0; k < NFEAT; k++) {
            float dk = sd[k];
            r += (dk > dj) || (dk == dj && k < t);   // stable, descending
        }
        sord[r] = t;
    }
    __syncthreads();
    if (t < NFEAT) g_order[b][t] = sord[t];

    // compact present objects (in sorted order) into candidate list
    int j    = (t < NFEAT) ? sord[t] : -1;
    int flag = (t < NFEAT) ? (zpres[b * NFEAT + j] != 0) : 0;
    unsigned bal = __ballot_sync(0xffffffffu, flag);
    int lane = t & 31, w = t >> 5;
    if (lane == 0) swsum[w] = __popc(bal);
    __syncthreads();
    int base = 0;
    for (int i = 0; i < w; i++) base += swsum[i];
    if (flag) {
        int pos = base + __popc(bal & ((1u << lane) - 1u));
        const float* zw = zwhere + (size_t)(b * NFEAT + j) * 4;
        float cx = zw[0], cy = zw[1], ww = zw[2], hh = zw[3];
        ww = fmaxf(ww, 0.01f);
        hh = fmaxf(hh, 0.01f);
        float4 f;
        f.x = 2.0f * cx - 1.0f;
        f.y = 2.0f * cy - 1.0f;
        f.z = ww;
        f.w = hh;
        g_candf[b][pos] = f;
        g_candd[b][pos] = recon_idx(j);
    }
    if (t == 0) {
        int s = 0;
        for (int i = 0; i < 17; i++) s += swsum[i];
        g_ncand[b] = s;
    }
}

// ---------------- K2: per-pixel winner by geometry; mark needed decodes -----
__global__ void k_winner() {
    int blk = blockIdx.x;          // 0..255
    int b = blk >> 6;
    int ypair = blk & 63;
    int t = threadIdx.x;           // 256
    int y = ypair * 2 + (t >> 7);
    int x = t & 127;

    __shared__ float4 cf[NFEAT];
    __shared__ int    cd[NFEAT];
    int nc = g_ncand[b];
    for (int i = t; i < nc; i += 256) { cf[i] = g_candf[b][i]; cd[i] = g_candd[b][i]; }
    __syncthreads();

    float gx = -1.0f + x * (2.0f / 127.0f);
    float gy = -1.0f + y * (2.0f / 127.0f);

    int win = -1;
    for (int s = 0; s < nc; s++) {
        float4 p = cf[s];
        float u = (gx - p.x) / p.z;
        float v = (gy - p.y) / p.w;
        float px = (u + 1.0f) * 0.5f * 63.0f;
        float py = (v + 1.0f) * 0.5f * 63.0f;
        float x0 = floorf(px), y0 = floorf(py);
        float wx = px - x0, wy = py - y0;
        int xi = (int)x0, yi = (int)y0;
        bool vx0 = (xi >= 0) && (xi < OBJW);
        bool vx1 = (xi + 1 >= 0) && (xi + 1 < OBJW);
        bool vy0 = (yi >= 0) && (yi < OBJW);
        bool vy1 = (yi + 1 >= 0) && (yi + 1 < OBJW);
        bool wxp = wx > 0.0f, wyp = wy > 0.0f;
        bool cov = (vy0 && vx0) || (vy0 && vx1 && wxp) ||
                   (vy1 && vx0 && wyp) || (vy1 && vx1 && wxp && wyp);
        if (cov) {
            win = s;
            g_need[b][cd[s]] = 1;
            break;
        }
    }
    g_winner[b][y][x] = win;
}

// ---------------- K3: compact needed rows ----------------------------------
__global__ void k_compact() {
    int t = threadIdx.x;  // 544
    __shared__ int swsum[17];
    int flag = (t < NB * NOBJ) ? (((const unsigned char*)g_need)[t] ? 1 : 0) : 0;
    unsigned bal = __ballot_sync(0xffffffffu, flag);
    int lane = t & 31, w = t >> 5;
    if (lane == 0) swsum[w] = __popc(bal);
    __syncthreads();
    int base = 0;
    for (int i = 0; i < w; i++) base += swsum[i];
    if (flag) g_rows[base + __popc(bal & ((1u << lane) - 1u))] = t;
    if (t == 0) {
        int s = 0;
        for (int i = 0; i < 17; i++) s += swsum[i];
        g_nrows = s;
    }
}

// ---------------- K4: hidden layer (64 -> 512, relu) for needed rows -------
__global__ void k_hidden(const float* __restrict__ zwhat,
                         const float* __restrict__ W1,
                         const float* __restrict__ b1) {
    int slot = blockIdx.x;
    if (slot >= g_nrows) return;
    int row = g_rows[slot];        // b*135 + o, linear into z_what
    __shared__ float sz[ZD];
    int t = threadIdx.x;           // 128
    if (t < ZD) sz[t] = zwhat[row * ZD + t];
    __syncthreads();
#pragma unroll
    for (int l = 0; l < 4; l++) {
        int n = t + l * 128;
        float acc = b1[n];
#pragma unroll 16
        for (int k = 0; k < ZD; k++) acc = fmaf(sz[k], W1[k * HID + n], acc);
        g_h[slot][n] = fmaxf(acc, 0.0f);
    }
}

// ---------------- K5: main GEMM 512 -> 12288 + bias + sigmoid --------------
// tile: M=32 rows x N=256 cols, K-step 16; 256 threads, 32 acc/thread
__global__ __launch_bounds__(256) void k_gemm(const float* __restrict__ W2,
                                              const float* __restrict__ b2) {
    int nrows = g_nrows;
    int mbase = blockIdx.y * 32;
    if (mbase >= nrows) return;
    int n0 = blockIdx.x * 256;

    __shared__ float As[32][17];      // [m][k], padded
    __shared__ float Bs[16][256];

    int t  = threadIdx.x;
    int ty = t >> 6;                  // 0..3 -> rows ty*8 .. ty*8+7
    int tx = t & 63;                  // cols tx + 64*j

    float acc[8][4];
#pragma unroll
    for (int i = 0; i < 8; i++)
#pragma unroll
        for (int j = 0; j < 4; j++) acc[i][j] = 0.0f;

    for (int k0 = 0; k0 < HID; k0 += 16) {
#pragma unroll
        for (int l = 0; l < 2; l++) {
            int e = t + l * 256;      // 0..511
            int m = e >> 4, kk = e & 15;
            As[m][kk] = g_h[mbase + m][k0 + kk];
        }
#pragma unroll
        for (int l = 0; l < 4; l++) {
            int e = t + l * 256;      // 0..1023
            int kk = e >> 6, n4 = e & 63;
            float4 v = *(const float4*)&W2[(size_t)(k0 + kk) * NOUT + n0 + n4 * 4];
            *(float4*)&Bs[kk][n4 * 4] = v;
        }
        __syncthreads();
#pragma unroll
        for (int kk = 0; kk < 16; kk++) {
            float a[8], bb[4];
#pragma unroll
            for (int i = 0; i < 8; i++) a[i] = As[ty * 8 + i][kk];
#pragma unroll
            for (int j = 0; j < 4; j++) bb[j] = Bs[kk][tx + 64 * j];
#pragma unroll
            for (int i = 0; i < 8; i++)
#pragma unroll
                for (int j = 0; j < 4; j++) acc[i][j] = fmaf(a[i], bb[j], acc[i][j]);
        }
        __syncthreads();
    }

    float bias[4];
#pragma unroll
    for (int j = 0; j < 4; j++) bias[j] = b2[n0 + tx + 64 * j];
#pragma unroll
    for (int i = 0; i < 8; i++) {
        int slot = mbase + ty * 8 + i;
        if (slot < nrows) {
            int row = g_rows[slot];
            float* dst = &g_dec[row][n0];
#pragma unroll
            for (int j = 0; j < 4; j++) {
                float v = acc[i][j] + bias[j];
                dst[tx + 64 * j] = 1.0f / (1.0f + expf(-v));
            }
        }
    }
}

// ---------------- K6: final bilinear sample + composite --------------------
__global__ void k_sample(float* __restrict__ out) {
    int id = blockIdx.x * 256 + threadIdx.x;   // 65536 pixels
    int b = id >> 14;
    int y = (id >> 7) & 127;
    int x = id & 127;
    int s = g_winner[b][y][x];

    float val[3] = {0.0f, 0.0f, 0.0f};
    if (s >= 0) {
        float4 p = g_candf[b][s];
        int dec = g_candd[b][s];
        float gx = -1.0f + x * (2.0f / 127.0f);
        float gy = -1.0f + y * (2.0f / 127.0f);
        float u = (gx - p.x) / p.z;
        float v = (gy - p.y) / p.w;
        float px = (u + 1.0f) * 0.5f * 63.0f;
        float py = (v + 1.0f) * 0.5f * 63.0f;
        float x0 = floorf(px), y0 = floorf(py);
        float wx = px - x0, wy = py - y0;
        int xi = (int)x0, yi = (int)y0;
        bool vx0 = (xi >= 0) && (xi < OBJW);
        bool vx1 = (xi + 1 >= 0) && (xi + 1 < OBJW);
        bool vy0 = (yi >= 0) && (yi < OBJW);
        bool vy1 = (yi + 1 >= 0) && (yi + 1 < OBJW);
        float w00 = (vy0 && vx0) ? (1.0f - wy) * (1.0f - wx) : 0.0f;
        float w01 = (vy0 && vx1) ? (1.0f - wy) * wx : 0.0f;
        float w10 = (vy1 && vx0) ? wy * (1.0f - wx) : 0.0f;
        float w11 = (vy1 && vx1) ? wy * wx : 0.0f;
        int xc0 = min(max(xi, 0), 63),     xc1 = min(max(xi + 1, 0), 63);
        int yc0 = min(max(yi, 0), 63),     yc1 = min(max(yi + 1, 0), 63);
        const float* base = g_dec[b * NOBJ + dec];
#pragma unroll
        for (int c = 0; c < 3; c++) {
            const float* im = base + c * (OBJW * OBJW);
            val[c] = im[yc0 * OBJW + xc0] * w00 + im[yc0 * OBJW + xc1] * w01 +
                     im[yc1 * OBJW + xc0] * w10 + im[yc1 * OBJW + xc1] * w11;
        }
    }
#pragma unroll
    for (int c = 0; c < 3; c++)
        out[(((size_t)b * 3 + c) * IMGW + y) * IMGW + x] = val[c];
}

// ---------------------------------------------------------------------------
extern "C" void kernel_launch(void* const* d_in, const int* in_sizes, int n_in,
                              void* d_out, int out_size) {
    const float* z_what    = (const float*)d_in[0];
    const float* z_where   = (const float*)d_in[1];
    const float* z_depth   = (const float*)d_in[2];
    const float* W1        = (const float*)d_in[3];
    const float* b1        = (const float*)d_in[4];
    const float* W2        = (const float*)d_in[5];
    const float* b2        = (const float*)d_in[6];
    const int*   z_present = (const int*)d_in[7];
    float* out = (float*)d_out;

    k_sort<<<NB, 544>>>(z_depth, z_where, z_present);
    k_winner<<<256, 256>>>();
    k_compact<<<1, 544>>>();
    k_hidden<<<NFEAT, 128>>>(z_what, W1, b1);
    dim3 gg(NOUT / 256, (NFEAT + 31) / 32);
    k_gemm<<<gg, 256>>>(W2, b2);
    k_sample<<<256, 256>>>(out);
}

// round 5
// speedup vs baseline: 1.5006x; 1.5006x over previous
#include <cuda_runtime.h>
#include <cuda_bf16.h>
#include <cstdint>
#include <math.h>

#define NB    4
#define NOBJ  135
#define NFEAT 540
#define ZD    64
#define HID   512
#define NOUT  12288   // 3*64*64
#define IMGW  128
#define OBJW  64

// ================= scratch (device globals; no allocation allowed) =========
__device__ int           g_order[NB][NFEAT];
__device__ float4        g_candf[NB][NFEAT];
__device__ int           g_candd[NB][NFEAT];
__device__ int           g_ncand[NB];
__device__ unsigned char g_need[NB][NOBJ];
__device__ int           g_rows[640];
__device__ int           g_nrows;
__device__ __align__(16) __nv_bfloat16 g_hb[640][HID];   // hidden acts, bf16
__device__ __align__(16) float g_dec[NB*NOBJ][NOUT];
__device__ int           g_winner[NB][IMGW][IMGW];

__device__ __forceinline__ int recon_idx(int j) {
    if (j < 400) return j >> 2;
    if (j < 500) return 100 + ((j - 400) >> 2);
    if (j < 536) return 125 + ((j - 500) >> 2);
    return 134;
}
__device__ __forceinline__ uint32_t smem_u32(const void* p) {
    uint32_t a;
    asm("{ .reg .u64 t; cvta.to.shared.u64 t, %1; cvt.u32.u64 %0, t; }" : "=r"(a) : "l"(p));
    return a;
}
__device__ __forceinline__ uint32_t pkbf(float a, float b) {
    __nv_bfloat162 h = __floats2bfloat162_rn(a, b);
    return *(uint32_t*)&h;
}

// ---------------- K1: stable descending sort by depth + candidate compaction
__global__ void k_sort(const float* __restrict__ zdepth,
                       const float* __restrict__ zwhere,
                       const int*   __restrict__ zpres) {
    int b = blockIdx.x;
    __shared__ float sd[NFEAT];
    __shared__ int   sord[NFEAT];
    __shared__ int   swsum[17];
    int t = threadIdx.x;   // 544

    if (t < NFEAT) sd[t] = zdepth[b * NOBJ + recon_idx(t)];
    if (t < NOBJ)  g_need[b][t] = 0;
    __syncthreads();

    if (t < NFEAT) {
        float dj = sd[t];
        int r = 0;
        for (int k = 0; k < NFEAT; k++) {
            float dk = sd[k];
            r += (dk > dj) || (dk == dj && k < t);   // stable, descending
        }
        sord[r] = t;
    }
    __syncthreads();
    if (t < NFEAT) g_order[b][t] = sord[t];

    int j    = (t < NFEAT) ? sord[t] : -1;
    int flag = (t < NFEAT) ? (zpres[b * NFEAT + j] != 0) : 0;
    unsigned bal = __ballot_sync(0xffffffffu, flag);
    int lane = t & 31, w = t >> 5;
    if (lane == 0) swsum[w] = __popc(bal);
    __syncthreads();
    int base = 0;
    for (int i = 0; i < w; i++) base += swsum[i];
    if (flag) {
        int pos = base + __popc(bal & ((1u << lane) - 1u));
        const float* zw = zwhere + (size_t)(b * NFEAT + j) * 4;
        float cx = zw[0], cy = zw[1], ww = zw[2], hh = zw[3];
        ww = fmaxf(ww, 0.01f);
        hh = fmaxf(hh, 0.01f);
        float4 f;
        f.x = 2.0f * cx - 1.0f;
        f.y = 2.0f * cy - 1.0f;
        f.z = ww;
        f.w = hh;
        g_candf[b][pos] = f;
        g_candd[b][pos] = recon_idx(j);
    }
    if (t == 0) {
        int s = 0;
        for (int i = 0; i < 17; i++) s += swsum[i];
        g_ncand[b] = s;
    }
}

// ---------------- K2: per-pixel winner by geometry --------------------------
__global__ void k_winner() {
    int blk = blockIdx.x;
    int b = blk >> 6;
    int ypair = blk & 63;
    int t = threadIdx.x;
    int y = ypair * 2 + (t >> 7);
    int x = t & 127;

    __shared__ float4 cf[NFEAT];
    __shared__ int    cd[NFEAT];
    int nc = g_ncand[b];
    for (int i = t; i < nc; i += 256) { cf[i] = g_candf[b][i]; cd[i] = g_candd[b][i]; }
    __syncthreads();

    float gx = -1.0f + x * (2.0f / 127.0f);
    float gy = -1.0f + y * (2.0f / 127.0f);

    int win = -1;
    for (int s = 0; s < nc; s++) {
        float4 p = cf[s];
        float u = (gx - p.x) / p.z;
        float v = (gy - p.y) / p.w;
        float px = (u + 1.0f) * 0.5f * 63.0f;
        float py = (v + 1.0f) * 0.5f * 63.0f;
        float x0 = floorf(px), y0 = floorf(py);
        float wx = px - x0, wy = py - y0;
        int xi = (int)x0, yi = (int)y0;
        bool vx0 = (xi >= 0) && (xi < OBJW);
        bool vx1 = (xi + 1 >= 0) && (xi + 1 < OBJW);
        bool vy0 = (yi >= 0) && (yi < OBJW);
        bool vy1 = (yi + 1 >= 0) && (yi + 1 < OBJW);
        bool wxp = wx > 0.0f, wyp = wy > 0.0f;
        bool cov = (vy0 && vx0) || (vy0 && vx1 && wxp) ||
                   (vy1 && vx0 && wyp) || (vy1 && vx1 && wxp && wyp);
        if (cov) {
            win = s;
            g_need[b][cd[s]] = 1;
            break;
        }
    }
    g_winner[b][y][x] = win;
}

// ---------------- K3: compact needed rows ----------------------------------
__global__ void k_compact() {
    int t = threadIdx.x;  // 544
    __shared__ int swsum[17];
    int flag = (t < NB * NOBJ) ? (((const unsigned char*)g_need)[t] ? 1 : 0) : 0;
    unsigned bal = __ballot_sync(0xffffffffu, flag);
    int lane = t & 31, w = t >> 5;
    if (lane == 0) swsum[w] = __popc(bal);
    __syncthreads();
    int base = 0;
    for (int i = 0; i < w; i++) base += swsum[i];
    if (flag) g_rows[base + __popc(bal & ((1u << lane) - 1u))] = t;
    if (t == 0) {
        int s = 0;
        for (int i = 0; i < 17; i++) s += swsum[i];
        g_nrows = s;
    }
}

// ---------------- K4: hidden layer 64->512 relu, tiled, bf16 out -----------
__global__ __launch_bounds__(256) void k_hidden(const float* __restrict__ zwhat,
                                                const float* __restrict__ W1,
                                                const float* __restrict__ b1) {
    __shared__ float sA[32][65];
    __shared__ float sW[64][132];
    int nt = blockIdx.x, mt = blockIdx.y;
    int nrows = g_nrows;
    int t = threadIdx.x;

#pragma unroll
    for (int l = 0; l < 8; l++) {
        int id = t + l * 256;           // A tile 32x64
        int m = id >> 6, k = id & 63;
        int slot = mt * 32 + m;
        sA[m][k] = (slot < nrows) ? zwhat[(size_t)g_rows[slot] * ZD + k] : 0.0f;
    }
#pragma unroll
    for (int l = 0; l < 8; l++) {
        int id = t + l * 256;           // W tile 64x128 (float4)
        int k = id >> 5, c4 = id & 31;
        float4 v = *(const float4*)&W1[(size_t)k * HID + nt * 128 + c4 * 4];
        *(float4*)&sW[k][c4 * 4] = v;
    }
    __syncthreads();

    int tm = t >> 5, tn = t & 31;
    float acc[4][4];
#pragma unroll
    for (int i = 0; i < 4; i++)
#pragma unroll
        for (int j = 0; j < 4; j++) acc[i][j] = 0.0f;

#pragma unroll 8
    for (int k = 0; k < 64; k++) {
        float a[4], w[4];
#pragma unroll
        for (int i = 0; i < 4; i++) a[i] = sA[tm * 4 + i][k];
#pragma unroll
        for (int j = 0; j < 4; j++) w[j] = sW[k][tn * 4 + j];
#pragma unroll
        for (int i = 0; i < 4; i++)
#pragma unroll
            for (int j = 0; j < 4; j++) acc[i][j] = fmaf(a[i], w[j], acc[i][j]);
    }

#pragma unroll
    for (int i = 0; i < 4; i++) {
        int slot = mt * 32 + tm * 4 + i;
#pragma unroll
        for (int j = 0; j < 4; j++) {
            int n = nt * 128 + tn * 4 + j;
            float v = fmaxf(acc[i][j] + b1[n], 0.0f);
            g_hb[slot][n] = __float2bfloat16(v);
        }
    }
}

// ---------------- K5: HMMA bf16 GEMM 512 -> 12288 + bias + sigmoid ---------
// CTA 128x128, 8 warps (4M x 2N), warp tile 32x64, K-chunks of 32,
// double-buffered smem + register prefetch.
#define ASTR 40    // bf16 units per A row (80 B, bank phase 5)
#define BSTR 136   // bf16 units per B row (272 B, bank phase 17)

__device__ __forceinline__ void ldsm4(uint32_t* r, uint32_t addr) {
    asm volatile("ldmatrix.sync.aligned.m8n8.x4.shared.b16 {%0,%1,%2,%3}, [%4];"
                 : "=r"(r[0]), "=r"(r[1]), "=r"(r[2]), "=r"(r[3]) : "r"(addr));
}
__device__ __forceinline__ void ldsm4t(uint32_t* r, uint32_t addr) {
    asm volatile("ldmatrix.sync.aligned.m8n8.x4.trans.shared.b16 {%0,%1,%2,%3}, [%4];"
                 : "=r"(r[0]), "=r"(r[1]), "=r"(r[2]), "=r"(r[3]) : "r"(addr));
}
__device__ __forceinline__ void mma16816(float* d, const uint32_t* a,
                                         uint32_t b0, uint32_t b1) {
    asm volatile("mma.sync.aligned.m16n8k16.row.col.f32.bf16.bf16.f32 "
                 "{%0,%1,%2,%3}, {%4,%5,%6,%7}, {%8,%9}, {%0,%1,%2,%3};"
                 : "+f"(d[0]), "+f"(d[1]), "+f"(d[2]), "+f"(d[3])
                 : "r"(a[0]), "r"(a[1]), "r"(a[2]), "r"(a[3]), "r"(b0), "r"(b1));
}

__global__ __launch_bounds__(256) void k_gemm_mma(const float* __restrict__ W2,
                                                  const float* __restrict__ b2) {
    int nrows = g_nrows;
    int mbase = blockIdx.y * 128;
    if (mbase >= nrows) return;
    int n0 = blockIdx.x * 128;

    __shared__ __nv_bfloat16 sA[2][128 * ASTR];
    __shared__ __nv_bfloat16 sB[2][32 * BSTR];

    int t = threadIdx.x, wid = t >> 5, lane = t & 31;
    int warpM = wid & 3, warpN = wid >> 2;

    float acc[2][8][4];
#pragma unroll
    for (int mi = 0; mi < 2; mi++)
#pragma unroll
        for (int n8 = 0; n8 < 8; n8++)
#pragma unroll
            for (int r = 0; r < 4; r++) acc[mi][n8][r] = 0.0f;

    uint4  aReg[2];
    float4 bReg[4];

    // ---- prefetch chunk 0 into regs, then smem buf 0
#pragma unroll
    for (int l = 0; l < 2; l++) {
        int id = t + l * 256;                // 0..511: 8 bf16 each
        int m = id >> 2, kq = id & 3;
        aReg[l] = *(const uint4*)&g_hb[mbase + m][kq * 8];
    }
#pragma unroll
    for (int l = 0; l < 4; l++) {
        int id = t + l * 256;                // 0..1023: 4 floats each
        int k = id >> 5, c4 = id & 31;
        bReg[l] = *(const float4*)&W2[(size_t)k * NOUT + n0 + c4 * 4];
    }
    uint32_t aBase0 = smem_u32(sA[0]), aBase1 = smem_u32(sA[1]);
    uint32_t bBase0 = smem_u32(sB[0]), bBase1 = smem_u32(sB[1]);

#pragma unroll
    for (int l = 0; l < 2; l++) {
        int id = t + l * 256;
        int m = id >> 2, kq = id & 3;
        *(uint4*)((char*)sA[0] + m * 80 + kq * 16) = aReg[l];
    }
#pragma unroll
    for (int l = 0; l < 4; l++) {
        int id = t + l * 256;
        int k = id >> 5, c4 = id & 31;
        uint2 p;
        p.x = pkbf(bReg[l].x, bReg[l].y);
        p.y = pkbf(bReg[l].z, bReg[l].w);
        *(uint2*)((char*)sB[0] + k * 272 + c4 * 8) = p;
    }
    __syncthreads();

    for (int c = 0; c < 16; c++) {
        int cur = c & 1;
        if (c < 15) {
            int k0 = (c + 1) * 32;
#pragma unroll
            for (int l = 0; l < 2; l++) {
                int id = t + l * 256;
                int m = id >> 2, kq = id & 3;
                aReg[l] = *(const uint4*)&g_hb[mbase + m][k0 + kq * 8];
            }
#pragma unroll
            for (int l = 0; l < 4; l++) {
                int id = t + l * 256;
                int k = id >> 5, c4 = id & 31;
                bReg[l] = *(const float4*)&W2[(size_t)(k0 + k) * NOUT + n0 + c4 * 4];
            }
        }

        uint32_t aB = cur ? aBase1 : aBase0;
        uint32_t bB = cur ? bBase1 : bBase0;
#pragma unroll
        for (int ks = 0; ks < 2; ks++) {
            uint32_t afr[2][4];
#pragma unroll
            for (int mi = 0; mi < 2; mi++) {
                int row = warpM * 32 + mi * 16 + (lane & 15);
                ldsm4(afr[mi], aB + row * 80 + ks * 32 + (lane >> 4) * 16);
            }
#pragma unroll
            for (int nt = 0; nt < 4; nt++) {
                uint32_t bfr[4];
                int krow = ks * 16 + (lane & 15);
                ldsm4t(bfr, bB + krow * 272 + (warpN * 64 + nt * 16) * 2 + (lane >> 4) * 16);
#pragma unroll
                for (int mi = 0; mi < 2; mi++) {
                    mma16816(acc[mi][nt * 2 + 0], afr[mi], bfr[0], bfr[1]);
                    mma16816(acc[mi][nt * 2 + 1], afr[mi], bfr[2], bfr[3]);
                }
            }
        }
        __syncthreads();

        if (c < 15) {
            int nxt = cur ^ 1;
            char* dA = (char*)(nxt ? sA[1] : sA[0]);
            char* dB = (char*)(nxt ? sB[1] : sB[0]);
#pragma unroll
            for (int l = 0; l < 2; l++) {
                int id = t + l * 256;
                int m = id >> 2, kq = id & 3;
                *(uint4*)(dA + m * 80 + kq * 16) = aReg[l];
            }
#pragma unroll
            for (int l = 0; l < 4; l++) {
                int id = t + l * 256;
                int k = id >> 5, c4 = id & 31;
                uint2 p;
                p.x = pkbf(bReg[l].x, bReg[l].y);
                p.y = pkbf(bReg[l].z, bReg[l].w);
                *(uint2*)(dB + k * 272 + c4 * 8) = p;
            }
            __syncthreads();
        }
    }

    // ---- epilogue: bias + sigmoid, store via d-frag mapping
    int p = lane >> 2, q = lane & 3;
#pragma unroll
    for (int mi = 0; mi < 2; mi++) {
#pragma unroll
        for (int half = 0; half < 2; half++) {      // d0,d1 vs d2,d3 (row +8)
            int slot = mbase + warpM * 32 + mi * 16 + p + half * 8;
            if (slot < nrows) {
                int row = g_rows[slot];
#pragma unroll
                for (int n8 = 0; n8 < 8; n8++) {
                    int col = n0 + warpN * 64 + n8 * 8 + q * 2;
                    float2 bb = *(const float2*)&b2[col];
                    float v0 = acc[mi][n8][half * 2 + 0] + bb.x;
                    float v1 = acc[mi][n8][half * 2 + 1] + bb.y;
                    float2 o;
                    o.x = 1.0f / (1.0f + expf(-v0));
                    o.y = 1.0f / (1.0f + expf(-v1));
                    *(float2*)&g_dec[row][col] = o;
                }
            }
        }
    }
}

// ---------------- K6: final bilinear sample + composite --------------------
__global__ void k_sample(float* __restrict__ out) {
    int id = blockIdx.x * 256 + threadIdx.x;
    int b = id >> 14;
    int y = (id >> 7) & 127;
    int x = id & 127;
    int s = g_winner[b][y][x];

    float val[3] = {0.0f, 0.0f, 0.0f};
    if (s >= 0) {
        float4 p = g_candf[b][s];
        int dec = g_candd[b][s];
        float gx = -1.0f + x * (2.0f / 127.0f);
        float gy = -1.0f + y * (2.0f / 127.0f);
        float u = (gx - p.x) / p.z;
        float v = (gy - p.y) / p.w;
        float px = (u + 1.0f) * 0.5f * 63.0f;
        float py = (v + 1.0f) * 0.5f * 63.0f;
        float x0 = floorf(px), y0 = floorf(py);
        float wx = px - x0, wy = py - y0;
        int xi = (int)x0, yi = (int)y0;
        bool vx0 = (xi >= 0) && (xi < OBJW);
        bool vx1 = (xi + 1 >= 0) && (xi + 1 < OBJW);
        bool vy0 = (yi >= 0) && (yi < OBJW);
        bool vy1 = (yi + 1 >= 0) && (yi + 1 < OBJW);
        float w00 = (vy0 && vx0) ? (1.0f - wy) * (1.0f - wx) : 0.0f;
        float w01 = (vy0 && vx1) ? (1.0f - wy) * wx : 0.0f;
        float w10 = (vy1 && vx0) ? wy * (1.0f - wx) : 0.0f;
        float w11 = (vy1 && vx1) ? wy * wx : 0.0f;
        int xc0 = min(max(xi, 0), 63),     xc1 = min(max(xi + 1, 0), 63);
        int yc0 = min(max(yi, 0), 63),     yc1 = min(max(yi + 1, 0), 63);
        const float* base = g_dec[b * NOBJ + dec];
#pragma unroll
        for (int c = 0; c < 3; c++) {
            const float* im = base + c * (OBJW * OBJW);
            val[c] = im[yc0 * OBJW + xc0] * w00 + im[yc0 * OBJW + xc1] * w01 +
                     im[yc1 * OBJW + xc0] * w10 + im[yc1 * OBJW + xc1] * w11;
        }
    }
#pragma unroll
    for (int c = 0; c < 3; c++)
        out[(((size_t)b * 3 + c) * IMGW + y) * IMGW + x] = val[c];
}

// ---------------------------------------------------------------------------
extern "C" void kernel_launch(void* const* d_in, const int* in_sizes, int n_in,
                              void* d_out, int out_size) {
    const float* z_what    = (const float*)d_in[0];
    const float* z_where   = (const float*)d_in[1];
    const float* z_depth   = (const float*)d_in[2];
    const float* W1        = (const float*)d_in[3];
    const float* b1        = (const float*)d_in[4];
    const float* W2        = (const float*)d_in[5];
    const float* b2        = (const float*)d_in[6];
    const int*   z_present = (const int*)d_in[7];
    float* out = (float*)d_out;

    k_sort<<<NB, 544>>>(z_depth, z_where, z_present);
    k_winner<<<256, 256>>>();
    k_compact<<<1, 544>>>();
    k_hidden<<<dim3(4, 17), 256>>>(z_what, W1, b1);
    k_gemm_mma<<<dim3(96, 5), 256>>>(W2, b2);
    k_sample<<<256, 256>>>(out);
}

// round 7
// speedup vs baseline: 1.6269x; 1.0842x over previous
#include <cuda_runtime.h>
#include <cuda_bf16.h>
#include <cstdint>
#include <math.h>

#define NB    4
#define NOBJ  135
#define NFEAT 540
#define ZD    64
#define HID   512
#define NOUT  12288   // 3*64*64
#define IMGW  128
#define OBJW  64

// ================= scratch (device globals; no allocation allowed) =========
__device__ float4        g_candf[NB][NFEAT];
__device__ int           g_candd[NB][NFEAT];
__device__ int           g_ncand[NB];
__device__ int           g_need[NB][NOBJ];
__device__ int           g_rows[640];
__device__ int           g_nrows;
__device__ __align__(16) __nv_bfloat16 g_hb[640][HID];    // hidden acts, bf16
__device__ __align__(16) __nv_bfloat16 g_W2b[HID * NOUT]; // W2 in bf16
__device__ __align__(16) float g_dec[NB*NOBJ][NOUT];
__device__ int           g_winner[NB][IMGW][IMGW];

__device__ __forceinline__ int recon_idx(int j) {
    if (j < 400) return j >> 2;
    if (j < 500) return 100 + ((j - 400) >> 2);
    if (j < 536) return 125 + ((j - 500) >> 2);
    return 134;
}
__device__ __forceinline__ uint32_t smem_u32(const void* p) {
    uint32_t a;
    asm("{ .reg .u64 t; cvta.to.shared.u64 t, %1; cvt.u32.u64 %0, t; }" : "=r"(a) : "l"(p));
    return a;
}
__device__ __forceinline__ uint32_t pkbf(float a, float b) {
    __nv_bfloat162 h = __floats2bfloat162_rn(a, b);
    return *(uint32_t*)&h;
}
__device__ __forceinline__ void cpasync16(uint32_t saddr, const void* g) {
    asm volatile("cp.async.cg.shared.global [%0], [%1], 16;" :: "r"(saddr), "l"(g));
}
#define CP_COMMIT() asm volatile("cp.async.commit_group;" ::: "memory")
#define CP_WAIT(N)  asm volatile("cp.async.wait_group %0;" :: "n"(N) : "memory")

// ---------------- K1: sort/candidates (blocks 0-3) + W2->bf16 (blocks 4+) --
__global__ void k_sort(const float* __restrict__ zdepth,
                       const float* __restrict__ zwhere,
                       const int*   __restrict__ zpres,
                       const float* __restrict__ W2) {
    int t = threadIdx.x;   // 544

    if (blockIdx.x >= 4) {
        // W2 fp32 -> bf16 conversion, grid-stride over uint4 outputs
        int cid = (blockIdx.x - 4) * blockDim.x + t;
        const float4* src = (const float4*)W2;
        uint4* dst = (uint4*)g_W2b;
        for (int o = cid; o < (HID * NOUT) / 8; o += 1024 * 544) {
            float4 f0 = src[o * 2], f1 = src[o * 2 + 1];
            uint4 v;
            v.x = pkbf(f0.x, f0.y);
            v.y = pkbf(f0.z, f0.w);
            v.z = pkbf(f1.x, f1.y);
            v.w = pkbf(f1.z, f1.w);
            dst[o] = v;
        }
        return;
    }

    int b = blockIdx.x;
    __shared__ float sd[NFEAT];
    __shared__ int   sord[NFEAT];
    __shared__ int   swsum[17];

    if (b == 0 && t == 0) g_nrows = 0;
    if (t < NFEAT) sd[t] = zdepth[b * NOBJ + recon_idx(t)];
    if (t < NOBJ)  g_need[b][t] = 0;
    __syncthreads();

    if (t < NFEAT) {
        float dj = sd[t];
        int r = 0;
        for (int k = 0; k < NFEAT; k++) {
            float dk = sd[k];
            r += (dk > dj) || (dk == dj && k < t);   // stable, descending
        }
        sord[r] = t;
    }
    __syncthreads();

    int j    = (t < NFEAT) ? sord[t] : -1;
    int flag = (t < NFEAT) ? (zpres[b * NFEAT + j] != 0) : 0;
    unsigned bal = __ballot_sync(0xffffffffu, flag);
    int lane = t & 31, w = t >> 5;
    if (lane == 0) swsum[w] = __popc(bal);
    __syncthreads();
    int base = 0;
    for (int i = 0; i < w; i++) base += swsum[i];
    if (flag) {
        int pos = base + __popc(bal & ((1u << lane) - 1u));
        const float* zw = zwhere + (size_t)(b * NFEAT + j) * 4;
        float cx = zw[0], cy = zw[1], ww = zw[2], hh = zw[3];
        ww = fmaxf(ww, 0.01f);
        hh = fmaxf(hh, 0.01f);
        float4 f;
        f.x = 2.0f * cx - 1.0f;
        f.y = 2.0f * cy - 1.0f;
        f.z = ww;
        f.w = hh;
        g_candf[b][pos] = f;
        g_candd[b][pos] = recon_idx(j);
    }
    if (t == 0) {
        int s = 0;
        for (int i = 0; i < 17; i++) s += swsum[i];
        g_ncand[b] = s;
    }
}

// ---------------- K2: per-pixel winner + inline need-compaction ------------
__global__ void k_winner() {
    int blk = blockIdx.x;
    int b = blk >> 6;
    int ypair = blk & 63;
    int t = threadIdx.x;
    int y = ypair * 2 + (t >> 7);
    int x = t & 127;

    __shared__ float4 cf[NFEAT];
    __shared__ int    cd[NFEAT];
    int nc = g_ncand[b];
    for (int i = t; i < nc; i += 256) { cf[i] = g_candf[b][i]; cd[i] = g_candd[b][i]; }
    __syncthreads();

    float gx = -1.0f + x * (2.0f / 127.0f);
    float gy = -1.0f + y * (2.0f / 127.0f);

    int win = -1;
    for (int s = 0; s < nc; s++) {
        float4 p = cf[s];
        float u = (gx - p.x) / p.z;
        float v = (gy - p.y) / p.w;
        float px = (u + 1.0f) * 0.5f * 63.0f;
        float py = (v + 1.0f) * 0.5f * 63.0f;
        float x0 = floorf(px), y0 = floorf(py);
        float wx = px - x0, wy = py - y0;
        int xi = (int)x0, yi = (int)y0;
        bool vx0 = (xi >= 0) && (xi < OBJW);
        bool vx1 = (xi + 1 >= 0) && (xi + 1 < OBJW);
        bool vy0 = (yi >= 0) && (yi < OBJW);
        bool vy1 = (yi + 1 >= 0) && (yi + 1 < OBJW);
        bool wxp = wx > 0.0f, wyp = wy > 0.0f;
        bool cov = (vy0 && vx0) || (vy0 && vx1 && wxp) ||
                   (vy1 && vx0 && wyp) || (vy1 && vx1 && wxp && wyp);
        if (cov) {
            win = s;
            int d = cd[s];
            if (g_need[b][d] == 0) {
                if (atomicExch(&g_need[b][d], 1) == 0) {
                    int slot = atomicAdd(&g_nrows, 1);
                    g_rows[slot] = b * NOBJ + d;
                }
            }
            break;
        }
    }
    g_winner[b][y][x] = win;
}

// ---------------- K3: hidden layer 64->512 relu, tiled, bf16 out -----------
__global__ __launch_bounds__(256) void k_hidden(const float* __restrict__ zwhat,
                                                const float* __restrict__ W1,
                                                const float* __restrict__ b1) {
    __shared__ __align__(16) float sA[16][68];   // row stride 272 B (16-aligned)
    __shared__ __align__(16) float sW[64][132];
    int nt = blockIdx.x, mt = blockIdx.y;    // 4 x 34
    int nrows = g_nrows;
    int t = threadIdx.x;

    {   // A tile 16x64 = 256 float4
        int m = t >> 4, k4 = t & 15;
        int slot = mt * 16 + m;
        float4 v = make_float4(0.f, 0.f, 0.f, 0.f);
        if (slot < nrows) v = *(const float4*)&zwhat[(size_t)g_rows[slot] * ZD + k4 * 4];
        *(float4*)&sA[m][k4 * 4] = v;
    }
#pragma unroll
    for (int l = 0; l < 8; l++) {
        int id = t + l * 256;           // W tile 64x128 (2048 float4)
        int k = id >> 5, c4 = id & 31;
        float4 v = *(const float4*)&W1[(size_t)k * HID + nt * 128 + c4 * 4];
        *(float4*)&sW[k][c4 * 4] = v;
    }
    __syncthreads();

    int tm = t >> 5, tn = t & 31;       // rows tm*2.., cols tn*4..
    float acc[2][4];
#pragma unroll
    for (int i = 0; i < 2; i++)
#pragma unroll
        for (int j = 0; j < 4; j++) acc[i][j] = 0.0f;

#pragma unroll 8
    for (int k = 0; k < 64; k++) {
        float a[2], w[4];
#pragma unroll
        for (int i = 0; i < 2; i++) a[i] = sA[tm * 2 + i][k];
#pragma unroll
        for (int j = 0; j < 4; j++) w[j] = sW[k][tn * 4 + j];
#pragma unroll
        for (int i = 0; i < 2; i++)
#pragma unroll
            for (int j = 0; j < 4; j++) acc[i][j] = fmaf(a[i], w[j], acc[i][j]);
    }

#pragma unroll
    for (int i = 0; i < 2; i++) {
        int slot = mt * 16 + tm * 2 + i;
        int n = nt * 128 + tn * 4;
        float v0 = fmaxf(acc[i][0] + b1[n + 0], 0.0f);
        float v1 = fmaxf(acc[i][1] + b1[n + 1], 0.0f);
        float v2 = fmaxf(acc[i][2] + b1[n + 2], 0.0f);
        float v3 = fmaxf(acc[i][3] + b1[n + 3], 0.0f);
        uint2 pp;
        pp.x = pkbf(v0, v1);
        pp.y = pkbf(v2, v3);
        *(uint2*)&g_hb[slot][n] = pp;
    }
}

// ---------------- K4: HMMA bf16 GEMM 512 -> 12288 + bias + sigmoid ---------
// CTA 128x128, 8 warps (4M x 2N), K-chunks of 32, cp.async double buffer.
__device__ __forceinline__ void ldsm4(uint32_t* r, uint32_t addr) {
    asm volatile("ldmatrix.sync.aligned.m8n8.x4.shared.b16 {%0,%1,%2,%3}, [%4];"
                 : "=r"(r[0]), "=r"(r[1]), "=r"(r[2]), "=r"(r[3]) : "r"(addr));
}
__device__ __forceinline__ void ldsm4t(uint32_t* r, uint32_t addr) {
    asm volatile("ldmatrix.sync.aligned.m8n8.x4.trans.shared.b16 {%0,%1,%2,%3}, [%4];"
                 : "=r"(r[0]), "=r"(r[1]), "=r"(r[2]), "=r"(r[3]) : "r"(addr));
}
__device__ __forceinline__ void mma16816(float* d, const uint32_t* a,
                                         uint32_t b0, uint32_t b1) {
    asm volatile("mma.sync.aligned.m16n8k16.row.col.f32.bf16.bf16.f32 "
                 "{%0,%1,%2,%3}, {%4,%5,%6,%7}, {%8,%9}, {%0,%1,%2,%3};"
                 : "+f"(d[0]), "+f"(d[1]), "+f"(d[2]), "+f"(d[3])
                 : "r"(a[0]), "r"(a[1]), "r"(a[2]), "r"(a[3]), "r"(b0), "r"(b1));
}

__global__ __launch_bounds__(256) void k_gemm_mma(const float* __restrict__ b2) {
    int nrows = g_nrows;
    int mbase = blockIdx.y * 128;
    if (mbase >= nrows) return;
    int n0 = blockIdx.x * 128;

    __shared__ __align__(16) __nv_bfloat16 sA[2][128 * 40];   // row stride 80 B
    __shared__ __align__(16) __nv_bfloat16 sB[2][32 * 136];   // row stride 272 B

    int t = threadIdx.x, wid = t >> 5, lane = t & 31;
    int warpM = wid & 3, warpN = wid >> 2;

    uint32_t aBase[2] = { smem_u32(sA[0]), smem_u32(sA[1]) };
    uint32_t bBase[2] = { smem_u32(sB[0]), smem_u32(sB[1]) };

    float acc[2][8][4];
#pragma unroll
    for (int mi = 0; mi < 2; mi++)
#pragma unroll
        for (int n8 = 0; n8 < 8; n8++)
#pragma unroll
            for (int r = 0; r < 4; r++) acc[mi][n8][r] = 0.0f;

    // per-thread cp.async slots (2 A + 2 B per chunk)
    int idA0 = t, idA1 = t + 256;            // m = id>>2, kq = id&3
    int idB0 = t, idB1 = t + 256;            // k = id>>4, c16 = id&15

#define ISSUE_CHUNK(c, bi) do {                                              \
    int _k0 = (c) * 32;                                                      \
    { int m = idA0 >> 2, kq = idA0 & 3;                                      \
      cpasync16(aBase[bi] + m * 80 + kq * 16, &g_hb[mbase + m][_k0 + kq * 8]); } \
    { int m = idA1 >> 2, kq = idA1 & 3;                                      \
      cpasync16(aBase[bi] + m * 80 + kq * 16, &g_hb[mbase + m][_k0 + kq * 8]); } \
    { int k = idB0 >> 4, c16 = idB0 & 15;                                    \
      cpasync16(bBase[bi] + k * 272 + c16 * 16,                              \
                &g_W2b[(size_t)(_k0 + k) * NOUT + n0 + c16 * 8]); }          \
    { int k = idB1 >> 4, c16 = idB1 & 15;                                    \
      cpasync16(bBase[bi] + k * 272 + c16 * 16,                              \
                &g_W2b[(size_t)(_k0 + k) * NOUT + n0 + c16 * 8]); }          \
    CP_COMMIT();                                                             \
} while (0)

    ISSUE_CHUNK(0, 0);

    for (int c = 0; c < 16; c++) {
        int cur = c & 1;
        if (c < 15) ISSUE_CHUNK(c + 1, cur ^ 1);
        if (c < 15) CP_WAIT(1); else CP_WAIT(0);
        __syncthreads();

        uint32_t aB = aBase[cur], bB = bBase[cur];
#pragma unroll
        for (int ks = 0; ks < 2; ks++) {
            uint32_t afr[2][4];
#pragma unroll
            for (int mi = 0; mi < 2; mi++) {
                int row = warpM * 32 + mi * 16 + (lane & 15);
                ldsm4(afr[mi], aB + row * 80 + ks * 32 + (lane >> 4) * 16);
            }
#pragma unroll
            for (int nt = 0; nt < 4; nt++) {
                uint32_t bfr[4];
                int krow = ks * 16 + (lane & 15);
                ldsm4t(bfr, bB + krow * 272 + (warpN * 64 + nt * 16) * 2 + (lane >> 4) * 16);
#pragma unroll
                for (int mi = 0; mi < 2; mi++) {
                    mma16816(acc[mi][nt * 2 + 0], afr[mi], bfr[0], bfr[1]);
                    mma16816(acc[mi][nt * 2 + 1], afr[mi], bfr[2], bfr[3]);
                }
            }
        }
        __syncthreads();
    }

    // ---- epilogue: bias + sigmoid, store via d-frag mapping
    int p = lane >> 2, q = lane & 3;
#pragma unroll
    for (int mi = 0; mi < 2; mi++) {
#pragma unroll
        for (int half = 0; half < 2; half++) {
            int slot = mbase + warpM * 32 + mi * 16 + p + half * 8;
            if (slot < nrows) {
                int row = g_rows[slot];
#pragma unroll
                for (int n8 = 0; n8 < 8; n8++) {
                    int col = n0 + warpN * 64 + n8 * 8 + q * 2;
                    float2 bb = *(const float2*)&b2[col];
                    float v0 = acc[mi][n8][half * 2 + 0] + bb.x;
                    float v1 = acc[mi][n8][half * 2 + 1] + bb.y;
                    float2 o;
                    o.x = 1.0f / (1.0f + __expf(-v0));
                    o.y = 1.0f / (1.0f + __expf(-v1));
                    *(float2*)&g_dec[row][col] = o;
                }
            }
        }
    }
}

// ---------------- K5: final bilinear sample + composite --------------------
__global__ void k_sample(float* __restrict__ out) {
    int id = blockIdx.x * 256 + threadIdx.x;
    int b = id >> 14;
    int y = (id >> 7) & 127;
    int x = id & 127;
    int s = g_winner[b][y][x];

    float val[3] = {0.0f, 0.0f, 0.0f};
    if (s >= 0) {
        float4 p = g_candf[b][s];
        int dec = g_candd[b][s];
        float gx = -1.0f + x * (2.0f / 127.0f);
        float gy = -1.0f + y * (2.0f / 127.0f);
        float u = (gx - p.x) / p.z;
        float v = (gy - p.y) / p.w;
        float px = (u + 1.0f) * 0.5f * 63.0f;
        float py = (v + 1.0f) * 0.5f * 63.0f;
        float x0 = floorf(px), y0 = floorf(py);
        float wx = px - x0, wy = py - y0;
        int xi = (int)x0, yi = (int)y0;
        bool vx0 = (xi >= 0) && (xi < OBJW);
        bool vx1 = (xi + 1 >= 0) && (xi + 1 < OBJW);
        bool vy0 = (yi >= 0) && (yi < OBJW);
        bool vy1 = (yi + 1 >= 0) && (yi + 1 < OBJW);
        float w00 = (vy0 && vx0) ? (1.0f - wy) * (1.0f - wx) : 0.0f;
        float w01 = (vy0 && vx1) ? (1.0f - wy) * wx : 0.0f;
        float w10 = (vy1 && vx0) ? wy * (1.0f - wx) : 0.0f;
        float w11 = (vy1 && vx1) ? wy * wx : 0.0f;
        int xc0 = min(max(xi, 0), 63),     xc1 = min(max(xi + 1, 0), 63);
        int yc0 = min(max(yi, 0), 63),     yc1 = min(max(yi + 1, 0), 63);
        const float* base = g_dec[b * NOBJ + dec];
#pragma unroll
        for (int c = 0; c < 3; c++) {
            const float* im = base + c * (OBJW * OBJW);
            val[c] = im[yc0 * OBJW + xc0] * w00 + im[yc0 * OBJW + xc1] * w01 +
                     im[yc1 * OBJW + xc0] * w10 + im[yc1 * OBJW + xc1] * w11;
        }
    }
#pragma unroll
    for (int c = 0; c < 3; c++)
        out[(((size_t)b * 3 + c) * IMGW + y) * IMGW + x] = val[c];
}

// ---------------------------------------------------------------------------
extern "C" void kernel_launch(void* const* d_in, const int* in_sizes, int n_in,
                              void* d_out, int out_size) {
    const float* z_what    = (const float*)d_in[0];
    const float* z_where   = (const float*)d_in[1];
    const float* z_depth   = (const float*)d_in[2];
    const float* W1        = (const float*)d_in[3];
    const float* b1        = (const float*)d_in[4];
    const float* W2        = (const float*)d_in[5];
    const float* b2        = (const float*)d_in[6];
    const int*   z_present = (const int*)d_in[7];
    float* out = (float*)d_out;

    k_sort<<<4 + 1024, 544>>>(z_depth, z_where, z_present, W2);
    k_winner<<<256, 256>>>();
    k_hidden<<<dim3(4, 34), 256>>>(z_what, W1, b1);
    k_gemm_mma<<<dim3(96, 5), 256>>>(b2);
    k_sample<<<256, 256>>>(out);
}

// round 8
// speedup vs baseline: 1.6863x; 1.0366x over previous
#include <cuda_runtime.h>
#include <cuda_bf16.h>
#include <cstdint>
#include <math.h>

#define NB    4
#define NOBJ  135
#define NFEAT 540
#define ZD    64
#define HID   512
#define NOUT  12288   // 3*64*64
#define IMGW  128
#define OBJW  64

// ================= scratch (device globals; no allocation allowed) =========
__device__ float4        g_candf[NB][NFEAT];   // ax, ay, 1/w, 1/h
__device__ int           g_candd[NB][NFEAT];
__device__ int           g_ncand[NB];
__device__ int           g_need[NB][NOBJ];
__device__ int           g_rows[640];
__device__ int           g_nrows;
__device__ __align__(16) __nv_bfloat16 g_hb[640][HID];    // hidden acts, bf16
__device__ __align__(16) __nv_bfloat16 g_W2b[HID * NOUT]; // W2 in bf16
__device__ __align__(16) float g_dec[NB*NOBJ][NOUT];
__device__ int           g_winner[NB][IMGW][IMGW];

__device__ __forceinline__ int recon_idx(int j) {
    if (j < 400) return j >> 2;
    if (j < 500) return 100 + ((j - 400) >> 2);
    if (j < 536) return 125 + ((j - 500) >> 2);
    return 134;
}
__device__ __forceinline__ uint32_t smem_u32(const void* p) {
    uint32_t a;
    asm("{ .reg .u64 t; cvta.to.shared.u64 t, %1; cvt.u32.u64 %0, t; }" : "=r"(a) : "l"(p));
    return a;
}
__device__ __forceinline__ uint32_t pkbf(float a, float b) {
    __nv_bfloat162 h = __floats2bfloat162_rn(a, b);
    return *(uint32_t*)&h;
}
__device__ __forceinline__ void cpasync16(uint32_t saddr, const void* g) {
    asm volatile("cp.async.cg.shared.global [%0], [%1], 16;" :: "r"(saddr), "l"(g));
}
#define CP_COMMIT() asm volatile("cp.async.commit_group;" ::: "memory")
#define CP_WAIT(N)  asm volatile("cp.async.wait_group %0;" :: "n"(N) : "memory")

// ---------------- K1: sort/candidates (blocks 0-3) + W2->bf16 (blocks 4+) --
__global__ void k_sort(const float* __restrict__ zdepth,
                       const float* __restrict__ zwhere,
                       const int*   __restrict__ zpres,
                       const float* __restrict__ W2) {
    int t = threadIdx.x;   // 544

    if (blockIdx.x >= 4) {
        // W2 fp32 -> bf16 conversion, grid-stride over uint4 outputs
        int cid = (blockIdx.x - 4) * blockDim.x + t;
        const float4* src = (const float4*)W2;
        uint4* dst = (uint4*)g_W2b;
        for (int o = cid; o < (HID * NOUT) / 8; o += 1024 * 544) {
            float4 f0 = src[o * 2], f1 = src[o * 2 + 1];
            uint4 v;
            v.x = pkbf(f0.x, f0.y);
            v.y = pkbf(f0.z, f0.w);
            v.z = pkbf(f1.x, f1.y);
            v.w = pkbf(f1.z, f1.w);
            dst[o] = v;
        }
        return;
    }

    int b = blockIdx.x;
    __shared__ float sd[NFEAT];
    __shared__ int   sord[NFEAT];
    __shared__ int   swsum[17];

    if (b == 0 && t == 0) g_nrows = 0;
    if (t < NFEAT) sd[t] = zdepth[b * NOBJ + recon_idx(t)];
    if (t < NOBJ)  g_need[b][t] = 0;
    __syncthreads();

    if (t < NFEAT) {
        float dj = sd[t];
        int r = 0;
        for (int k = 0; k < NFEAT; k++) {
            float dk = sd[k];
            r += (dk > dj) || (dk == dj && k < t);   // stable, descending
        }
        sord[r] = t;
    }
    __syncthreads();

    int j    = (t < NFEAT) ? sord[t] : -1;
    int flag = (t < NFEAT) ? (zpres[b * NFEAT + j] != 0) : 0;
    unsigned bal = __ballot_sync(0xffffffffu, flag);
    int lane = t & 31, w = t >> 5;
    if (lane == 0) swsum[w] = __popc(bal);
    __syncthreads();
    int base = 0;
    for (int i = 0; i < w; i++) base += swsum[i];
    if (flag) {
        int pos = base + __popc(bal & ((1u << lane) - 1u));
        const float* zw = zwhere + (size_t)(b * NFEAT + j) * 4;
        float cx = zw[0], cy = zw[1], ww = zw[2], hh = zw[3];
        ww = fmaxf(ww, 0.01f);
        hh = fmaxf(hh, 0.01f);
        float4 f;
        f.x = 2.0f * cx - 1.0f;
        f.y = 2.0f * cy - 1.0f;
        f.z = 1.0f / ww;               // reciprocal: winner/sample use FMUL
        f.w = 1.0f / hh;
        g_candf[b][pos] = f;
        g_candd[b][pos] = recon_idx(j);
    }
    if (t == 0) {
        int s = 0;
        for (int i = 0; i < 17; i++) s += swsum[i];
        g_ncand[b] = s;
    }
}

// ---------------- K2: per-pixel winner + inline need-compaction ------------
__global__ void k_winner() {
    int blk = blockIdx.x;
    int b = blk >> 6;
    int ypair = blk & 63;
    int t = threadIdx.x;
    int y = ypair * 2 + (t >> 7);
    int x = t & 127;

    __shared__ float4 cf[NFEAT];
    __shared__ int    cd[NFEAT];
    int nc = g_ncand[b];
    for (int i = t; i < nc; i += 256) { cf[i] = g_candf[b][i]; cd[i] = g_candd[b][i]; }
    __syncthreads();

    float gx = -1.0f + x * (2.0f / 127.0f);
    float gy = -1.0f + y * (2.0f / 127.0f);

    int win = -1;
    for (int s = 0; s < nc; s++) {
        float4 p = cf[s];
        float u = (gx - p.x) * p.z;
        float v = (gy - p.y) * p.w;
        float px = (u + 1.0f) * 0.5f * 63.0f;
        float py = (v + 1.0f) * 0.5f * 63.0f;
        float x0 = floorf(px), y0 = floorf(py);
        float wx = px - x0, wy = py - y0;
        int xi = (int)x0, yi = (int)y0;
        bool vx0 = (xi >= 0) && (xi < OBJW);
        bool vx1 = (xi + 1 >= 0) && (xi + 1 < OBJW);
        bool vy0 = (yi >= 0) && (yi < OBJW);
        bool vy1 = (yi + 1 >= 0) && (yi + 1 < OBJW);
        bool wxp = wx > 0.0f, wyp = wy > 0.0f;
        bool cov = (vy0 && vx0) || (vy0 && vx1 && wxp) ||
                   (vy1 && vx0 && wyp) || (vy1 && vx1 && wxp && wyp);
        if (cov) {
            win = s;
            int d = cd[s];
            if (g_need[b][d] == 0) {
                if (atomicExch(&g_need[b][d], 1) == 0) {
                    int slot = atomicAdd(&g_nrows, 1);
                    g_rows[slot] = b * NOBJ + d;
                }
            }
            break;
        }
    }
    g_winner[b][y][x] = win;
}

// ---------------- K3: hidden layer 64->512 relu, tiled, bf16 out -----------
__global__ __launch_bounds__(256) void k_hidden(const float* __restrict__ zwhat,
                                                const float* __restrict__ W1,
                                                const float* __restrict__ b1) {
    __shared__ __align__(16) float sA[16][68];   // row stride 272 B (16-aligned)
    __shared__ __align__(16) float sW[64][132];
    int nt = blockIdx.x, mt = blockIdx.y;    // 4 x 34
    int nrows = g_nrows;
    int t = threadIdx.x;

    {   // A tile 16x64 = 256 float4
        int m = t >> 4, k4 = t & 15;
        int slot = mt * 16 + m;
        float4 v = make_float4(0.f, 0.f, 0.f, 0.f);
        if (slot < nrows) v = *(const float4*)&zwhat[(size_t)g_rows[slot] * ZD + k4 * 4];
        *(float4*)&sA[m][k4 * 4] = v;
    }
#pragma unroll
    for (int l = 0; l < 8; l++) {
        int id = t + l * 256;           // W tile 64x128 (2048 float4)
        int k = id >> 5, c4 = id & 31;
        float4 v = *(const float4*)&W1[(size_t)k * HID + nt * 128 + c4 * 4];
        *(float4*)&sW[k][c4 * 4] = v;
    }
    __syncthreads();

    int tm = t >> 5, tn = t & 31;       // rows tm*2.., cols tn*4..
    float acc[2][4];
#pragma unroll
    for (int i = 0; i < 2; i++)
#pragma unroll
        for (int j = 0; j < 4; j++) acc[i][j] = 0.0f;

#pragma unroll 8
    for (int k = 0; k < 64; k++) {
        float a[2], w[4];
#pragma unroll
        for (int i = 0; i < 2; i++) a[i] = sA[tm * 2 + i][k];
#pragma unroll
        for (int j = 0; j < 4; j++) w[j] = sW[k][tn * 4 + j];
#pragma unroll
        for (int i = 0; i < 2; i++)
#pragma unroll
            for (int j = 0; j < 4; j++) acc[i][j] = fmaf(a[i], w[j], acc[i][j]);
    }

#pragma unroll
    for (int i = 0; i < 2; i++) {
        int slot = mt * 16 + tm * 2 + i;
        int n = nt * 128 + tn * 4;
        float v0 = fmaxf(acc[i][0] + b1[n + 0], 0.0f);
        float v1 = fmaxf(acc[i][1] + b1[n + 1], 0.0f);
        float v2 = fmaxf(acc[i][2] + b1[n + 2], 0.0f);
        float v3 = fmaxf(acc[i][3] + b1[n + 3], 0.0f);
        uint2 pp;
        pp.x = pkbf(v0, v1);
        pp.y = pkbf(v2, v3);
        *(uint2*)&g_hb[slot][n] = pp;
    }
}

// ---------------- K4: HMMA bf16 GEMM 512 -> 12288 + bias + sigmoid ---------
// CTA 128x128, 8 warps (4M x 2N), K-chunks of 32, 4-stage cp.async pipeline.
#define ASTB 10240          // bytes per A stage (128 rows x 80 B)
#define BSTB 8704           // bytes per B stage (32 rows x 272 B)
#define NSTG 4
#define GEMM_DSMEM (NSTG * (ASTB + BSTB))   // 75776

__device__ __forceinline__ void ldsm4(uint32_t* r, uint32_t addr) {
    asm volatile("ldmatrix.sync.aligned.m8n8.x4.shared.b16 {%0,%1,%2,%3}, [%4];"
                 : "=r"(r[0]), "=r"(r[1]), "=r"(r[2]), "=r"(r[3]) : "r"(addr));
}
__device__ __forceinline__ void ldsm4t(uint32_t* r, uint32_t addr) {
    asm volatile("ldmatrix.sync.aligned.m8n8.x4.trans.shared.b16 {%0,%1,%2,%3}, [%4];"
                 : "=r"(r[0]), "=r"(r[1]), "=r"(r[2]), "=r"(r[3]) : "r"(addr));
}
__device__ __forceinline__ void mma16816(float* d, const uint32_t* a,
                                         uint32_t b0, uint32_t b1) {
    asm volatile("mma.sync.aligned.m16n8k16.row.col.f32.bf16.bf16.f32 "
                 "{%0,%1,%2,%3}, {%4,%5,%6,%7}, {%8,%9}, {%0,%1,%2,%3};"
                 : "+f"(d[0]), "+f"(d[1]), "+f"(d[2]), "+f"(d[3])
                 : "r"(a[0]), "r"(a[1]), "r"(a[2]), "r"(a[3]), "r"(b0), "r"(b1));
}

__global__ __launch_bounds__(256) void k_gemm_mma(const float* __restrict__ b2) {
    int nrows = g_nrows;
    int mbase = blockIdx.y * 128;
    if (mbase >= nrows) return;
    int n0 = blockIdx.x * 128;

    extern __shared__ __align__(16) char dsm[];
    uint32_t smBase = smem_u32(dsm);

    int t = threadIdx.x, wid = t >> 5, lane = t & 31;
    int warpM = wid & 3, warpN = wid >> 2;

    float acc[2][8][4];
#pragma unroll
    for (int mi = 0; mi < 2; mi++)
#pragma unroll
        for (int n8 = 0; n8 < 8; n8++)
#pragma unroll
            for (int r = 0; r < 4; r++) acc[mi][n8][r] = 0.0f;

    // per-thread cp.async slot indices
    int mA0 = t >> 2,        kqA0 = t & 3;
    int mA1 = (t + 256) >> 2, kqA1 = (t + 256) & 3;
    int kB0 = t >> 4,        cB0 = t & 15;
    int kB1 = (t + 256) >> 4, cB1 = (t + 256) & 15;

#define ISSUE_CHUNK(c, st) do {                                                \
    int _k0 = (c) * 32;                                                        \
    uint32_t _aB = smBase + (st) * ASTB;                                       \
    uint32_t _bB = smBase + NSTG * ASTB + (st) * BSTB;                         \
    cpasync16(_aB + mA0 * 80 + kqA0 * 16, &g_hb[mbase + mA0][_k0 + kqA0 * 8]); \
    cpasync16(_aB + mA1 * 80 + kqA1 * 16, &g_hb[mbase + mA1][_k0 + kqA1 * 8]); \
    cpasync16(_bB + kB0 * 272 + cB0 * 16,                                      \
              &g_W2b[(size_t)(_k0 + kB0) * NOUT + n0 + cB0 * 8]);              \
    cpasync16(_bB + kB1 * 272 + cB1 * 16,                                      \
              &g_W2b[(size_t)(_k0 + kB1) * NOUT + n0 + cB1 * 8]);              \
    CP_COMMIT();                                                               \
} while (0)

    ISSUE_CHUNK(0, 0);
    ISSUE_CHUNK(1, 1);
    ISSUE_CHUNK(2, 2);

    for (int c = 0; c < 16; c++) {
        int st = c & 3;
        CP_WAIT(2);                 // chunk c has landed
        __syncthreads();            // all warps done with stage (c-1)&3
        if (c < 13) ISSUE_CHUNK(c + 3, (c + 3) & 3);
        else        CP_COMMIT();    // empty group keeps wait-count invariant

        uint32_t aB = smBase + st * ASTB;
        uint32_t bB = smBase + NSTG * ASTB + st * BSTB;
#pragma unroll
        for (int ks = 0; ks < 2; ks++) {
            uint32_t afr[2][4];
#pragma unroll
            for (int mi = 0; mi < 2; mi++) {
                int row = warpM * 32 + mi * 16 + (lane & 15);
                ldsm4(afr[mi], aB + row * 80 + ks * 32 + (lane >> 4) * 16);
            }
#pragma unroll
            for (int nt = 0; nt < 4; nt++) {
                uint32_t bfr[4];
                int krow = ks * 16 + (lane & 15);
                ldsm4t(bfr, bB + krow * 272 + (warpN * 64 + nt * 16) * 2 + (lane >> 4) * 16);
#pragma unroll
                for (int mi = 0; mi < 2; mi++) {
                    mma16816(acc[mi][nt * 2 + 0], afr[mi], bfr[0], bfr[1]);
                    mma16816(acc[mi][nt * 2 + 1], afr[mi], bfr[2], bfr[3]);
                }
            }
        }
    }

    // ---- epilogue: bias + sigmoid, store via d-frag mapping
    int p = lane >> 2, q = lane & 3;
#pragma unroll
    for (int mi = 0; mi < 2; mi++) {
#pragma unroll
        for (int half = 0; half < 2; half++) {
            int slot = mbase + warpM * 32 + mi * 16 + p + half * 8;
            if (slot < nrows) {
                int row = g_rows[slot];
#pragma unroll
                for (int n8 = 0; n8 < 8; n8++) {
                    int col = n0 + warpN * 64 + n8 * 8 + q * 2;
                    float2 bb = *(const float2*)&b2[col];
                    float v0 = acc[mi][n8][half * 2 + 0] + bb.x;
                    float v1 = acc[mi][n8][half * 2 + 1] + bb.y;
                    float2 o;
                    o.x = 1.0f / (1.0f + __expf(-v0));
                    o.y = 1.0f / (1.0f + __expf(-v1));
                    *(float2*)&g_dec[row][col] = o;
                }
            }
        }
    }
}

// ---------------- K5: final bilinear sample + composite --------------------
__global__ void k_sample(float* __restrict__ out) {
    int id = blockIdx.x * 256 + threadIdx.x;
    int b = id >> 14;
    int y = (id >> 7) & 127;
    int x = id & 127;
    int s = g_winner[b][y][x];

    float val[3] = {0.0f, 0.0f, 0.0f};
    if (s >= 0) {
        float4 p = g_candf[b][s];
        int dec = g_candd[b][s];
        float gx = -1.0f + x * (2.0f / 127.0f);
        float gy = -1.0f + y * (2.0f / 127.0f);
        float u = (gx - p.x) * p.z;
        float v = (gy - p.y) * p.w;
        float px = (u + 1.0f) * 0.5f * 63.0f;
        float py = (v + 1.0f) * 0.5f * 63.0f;
        float x0 = floorf(px), y0 = floorf(py);
        float wx = px - x0, wy = py - y0;
        int xi = (int)x0, yi = (int)y0;
        bool vx0 = (xi >= 0) && (xi < OBJW);
        bool vx1 = (xi + 1 >= 0) && (xi + 1 < OBJW);
        bool vy0 = (yi >= 0) && (yi < OBJW);
        bool vy1 = (yi + 1 >= 0) && (yi + 1 < OBJW);
        float w00 = (vy0 && vx0) ? (1.0f - wy) * (1.0f - wx) : 0.0f;
        float w01 = (vy0 && vx1) ? (1.0f - wy) * wx : 0.0f;
        float w10 = (vy1 && vx0) ? wy * (1.0f - wx) : 0.0f;
        float w11 = (vy1 && vx1) ? wy * wx : 0.0f;
        int xc0 = min(max(xi, 0), 63),     xc1 = min(max(xi + 1, 0), 63);
        int yc0 = min(max(yi, 0), 63),     yc1 = min(max(yi + 1, 0), 63);
        const float* base = g_dec[b * NOBJ + dec];
#pragma unroll
        for (int c = 0; c < 3; c++) {
            const float* im = base + c * (OBJW * OBJW);
            val[c] = im[yc0 * OBJW + xc0] * w00 + im[yc0 * OBJW + xc1] * w01 +
                     im[yc1 * OBJW + xc0] * w10 + im[yc1 * OBJW + xc1] * w11;
        }
    }
#pragma unroll
    for (int c = 0; c < 3; c++)
        out[(((size_t)b * 3 + c) * IMGW + y) * IMGW + x] = val[c];
}

// ---------------------------------------------------------------------------
extern "C" void kernel_launch(void* const* d_in, const int* in_sizes, int n_in,
                              void* d_out, int out_size) {
    const float* z_what    = (const float*)d_in[0];
    const float* z_where   = (const float*)d_in[1];
    const float* z_depth   = (const float*)d_in[2];
    const float* W1        = (const float*)d_in[3];
    const float* b1        = (const float*)d_in[4];
    const float* W2        = (const float*)d_in[5];
    const float* b2        = (const float*)d_in[6];
    const int*   z_present = (const int*)d_in[7];
    float* out = (float*)d_out;

    static int attr_done = 0;
    if (!attr_done) {
        cudaFuncSetAttribute(k_gemm_mma,
                             cudaFuncAttributeMaxDynamicSharedMemorySize, GEMM_DSMEM);
        attr_done = 1;
    }

    k_sort<<<4 + 1024, 544>>>(z_depth, z_where, z_present, W2);
    k_winner<<<256, 256>>>();
    k_hidden<<<dim3(4, 34), 256>>>(z_what, W1, b1);
    k_gemm_mma<<<dim3(96, 5), 256, GEMM_DSMEM>>>(b2);
    k_sample<<<256, 256>>>(out);
}

// round 9
// speedup vs baseline: 1.7585x; 1.0428x over previous
#include <cuda_runtime.h>
#include <cuda_bf16.h>
#include <cstdint>
#include <math.h>

#define NB    4
#define NOBJ  135
#define NFEAT 540
#define ZD    64
#define HID   512
#define NOUT  12288   // 3*64*64
#define IMGW  128
#define OBJW  64

// ================= scratch (device globals; no allocation allowed) =========
__device__ float4        g_candf[NB][NFEAT];   // ax, ay, 1/w, 1/h
__device__ int           g_candd[NB][NFEAT];
__device__ int           g_ncand[NB];
__device__ int           g_need[NB][NOBJ];
__device__ int           g_rows[640];
__device__ int           g_nrows;
__device__ __align__(16) __nv_bfloat16 g_hb[640][HID];    // hidden acts, bf16
__device__ __align__(16) __nv_bfloat16 g_W2b[HID * NOUT]; // W2 in bf16
__device__ __align__(16) float g_dec[NB*NOBJ][NOUT];
__device__ int           g_winner[NB][IMGW][IMGW];

__device__ __forceinline__ int recon_idx(int j) {
    if (j < 400) return j >> 2;
    if (j < 500) return 100 + ((j - 400) >> 2);
    if (j < 536) return 125 + ((j - 500) >> 2);
    return 134;
}
__device__ __forceinline__ uint32_t smem_u32(const void* p) {
    uint32_t a;
    asm("{ .reg .u64 t; cvta.to.shared.u64 t, %1; cvt.u32.u64 %0, t; }" : "=r"(a) : "l"(p));
    return a;
}
__device__ __forceinline__ uint32_t pkbf(float a, float b) {
    __nv_bfloat162 h = __floats2bfloat162_rn(a, b);
    return *(uint32_t*)&h;
}
__device__ __forceinline__ void cpasync16(uint32_t saddr, const void* g) {
    asm volatile("cp.async.cg.shared.global [%0], [%1], 16;" :: "r"(saddr), "l"(g));
}
#define CP_COMMIT() asm volatile("cp.async.commit_group;" ::: "memory")
#define CP_WAIT(N)  asm volatile("cp.async.wait_group %0;" :: "n"(N) : "memory")

// ---------------- K1: sort/candidates (blocks 0-3) + W2->bf16 (blocks 4+) --
__global__ void k_sort(const float* __restrict__ zdepth,
                       const float* __restrict__ zwhere,
                       const int*   __restrict__ zpres,
                       const float* __restrict__ W2) {
    int t = threadIdx.x;   // 544

    if (blockIdx.x >= 4) {
        // W2 fp32 -> bf16 conversion, grid-stride over uint4 outputs
        int cid = (blockIdx.x - 4) * blockDim.x + t;
        const float4* src = (const float4*)W2;
        uint4* dst = (uint4*)g_W2b;
        for (int o = cid; o < (HID * NOUT) / 8; o += 1024 * 544) {
            float4 f0 = src[o * 2], f1 = src[o * 2 + 1];
            uint4 v;
            v.x = pkbf(f0.x, f0.y);
            v.y = pkbf(f0.z, f0.w);
            v.z = pkbf(f1.x, f1.y);
            v.w = pkbf(f1.z, f1.w);
            dst[o] = v;
        }
        return;
    }

    int b = blockIdx.x;
    __shared__ float sd[NFEAT];
    __shared__ int   sord[NFEAT];
    __shared__ int   swsum[17];

    if (b == 0 && t == 0) g_nrows = 0;
    if (t < NFEAT) sd[t] = zdepth[b * NOBJ + recon_idx(t)];
    if (t < NOBJ)  g_need[b][t] = 0;
    __syncthreads();

    if (t < NFEAT) {
        float dj = sd[t];
        int r = 0;
        for (int k = 0; k < NFEAT; k++) {
            float dk = sd[k];
            r += (dk > dj) || (dk == dj && k < t);   // stable, descending
        }
        sord[r] = t;
    }
    __syncthreads();

    int j    = (t < NFEAT) ? sord[t] : -1;
    int flag = (t < NFEAT) ? (zpres[b * NFEAT + j] != 0) : 0;
    unsigned bal = __ballot_sync(0xffffffffu, flag);
    int lane = t & 31, w = t >> 5;
    if (lane == 0) swsum[w] = __popc(bal);
    __syncthreads();
    int base = 0;
    for (int i = 0; i < w; i++) base += swsum[i];
    if (flag) {
        int pos = base + __popc(bal & ((1u << lane) - 1u));
        const float* zw = zwhere + (size_t)(b * NFEAT + j) * 4;
        float cx = zw[0], cy = zw[1], ww = zw[2], hh = zw[3];
        ww = fmaxf(ww, 0.01f);
        hh = fmaxf(hh, 0.01f);
        float4 f;
        f.x = 2.0f * cx - 1.0f;
        f.y = 2.0f * cy - 1.0f;
        f.z = 1.0f / ww;               // reciprocal: winner/sample use FMUL
        f.w = 1.0f / hh;
        g_candf[b][pos] = f;
        g_candd[b][pos] = recon_idx(j);
    }
    if (t == 0) {
        int s = 0;
        for (int i = 0; i < 17; i++) s += swsum[i];
        g_ncand[b] = s;
    }
}

// ---------------- K2: per-pixel winner + inline need-compaction ------------
__global__ void k_winner() {
    int blk = blockIdx.x;
    int b = blk >> 6;
    int ypair = blk & 63;
    int t = threadIdx.x;
    int y = ypair * 2 + (t >> 7);
    int x = t & 127;

    __shared__ float4 cf[NFEAT];
    __shared__ int    cd[NFEAT];
    int nc = g_ncand[b];
    for (int i = t; i < nc; i += 256) { cf[i] = g_candf[b][i]; cd[i] = g_candd[b][i]; }
    __syncthreads();

    float gx = -1.0f + x * (2.0f / 127.0f);
    float gy = -1.0f + y * (2.0f / 127.0f);

    int win = -1;
    for (int s = 0; s < nc; s++) {
        float4 p = cf[s];
        float u = (gx - p.x) * p.z;
        float v = (gy - p.y) * p.w;
        float px = (u + 1.0f) * 0.5f * 63.0f;
        float py = (v + 1.0f) * 0.5f * 63.0f;
        float x0 = floorf(px), y0 = floorf(py);
        float wx = px - x0, wy = py - y0;
        int xi = (int)x0, yi = (int)y0;
        bool vx0 = (xi >= 0) && (xi < OBJW);
        bool vx1 = (xi + 1 >= 0) && (xi + 1 < OBJW);
        bool vy0 = (yi >= 0) && (yi < OBJW);
        bool vy1 = (yi + 1 >= 0) && (yi + 1 < OBJW);
        bool wxp = wx > 0.0f, wyp = wy > 0.0f;
        bool cov = (vy0 && vx0) || (vy0 && vx1 && wxp) ||
                   (vy1 && vx0 && wyp) || (vy1 && vx1 && wxp && wyp);
        if (cov) {
            win = s;
            int d = cd[s];
            if (g_need[b][d] == 0) {
                if (atomicExch(&g_need[b][d], 1) == 0) {
                    int slot = atomicAdd(&g_nrows, 1);
                    g_rows[slot] = b * NOBJ + d;
                }
            }
            break;
        }
    }
    g_winner[b][y][x] = win;
}

// ---------------- K3: hidden layer 64->512 relu, tiled, bf16 out -----------
__global__ __launch_bounds__(256) void k_hidden(const float* __restrict__ zwhat,
                                                const float* __restrict__ W1,
                                                const float* __restrict__ b1) {
    __shared__ __align__(16) float sA[16][68];   // row stride 272 B (16-aligned)
    __shared__ __align__(16) float sW[64][132];
    int nt = blockIdx.x, mt = blockIdx.y;    // 4 x 34
    int nrows = g_nrows;
    int t = threadIdx.x;

    {   // A tile 16x64 = 256 float4
        int m = t >> 4, k4 = t & 15;
        int slot = mt * 16 + m;
        float4 v = make_float4(0.f, 0.f, 0.f, 0.f);
        if (slot < nrows) v = *(const float4*)&zwhat[(size_t)g_rows[slot] * ZD + k4 * 4];
        *(float4*)&sA[m][k4 * 4] = v;
    }
#pragma unroll
    for (int l = 0; l < 8; l++) {
        int id = t + l * 256;           // W tile 64x128 (2048 float4)
        int k = id >> 5, c4 = id & 31;
        float4 v = *(const float4*)&W1[(size_t)k * HID + nt * 128 + c4 * 4];
        *(float4*)&sW[k][c4 * 4] = v;
    }
    __syncthreads();

    int tm = t >> 5, tn = t & 31;       // rows tm*2.., cols tn*4..
    float acc[2][4];
#pragma unroll
    for (int i = 0; i < 2; i++)
#pragma unroll
        for (int j = 0; j < 4; j++) acc[i][j] = 0.0f;

#pragma unroll 8
    for (int k = 0; k < 64; k++) {
        float a[2], w[4];
#pragma unroll
        for (int i = 0; i < 2; i++) a[i] = sA[tm * 2 + i][k];
#pragma unroll
        for (int j = 0; j < 4; j++) w[j] = sW[k][tn * 4 + j];
#pragma unroll
        for (int i = 0; i < 2; i++)
#pragma unroll
            for (int j = 0; j < 4; j++) acc[i][j] = fmaf(a[i], w[j], acc[i][j]);
    }

#pragma unroll
    for (int i = 0; i < 2; i++) {
        int slot = mt * 16 + tm * 2 + i;
        int n = nt * 128 + tn * 4;
        float v0 = fmaxf(acc[i][0] + b1[n + 0], 0.0f);
        float v1 = fmaxf(acc[i][1] + b1[n + 1], 0.0f);
        float v2 = fmaxf(acc[i][2] + b1[n + 2], 0.0f);
        float v3 = fmaxf(acc[i][3] + b1[n + 3], 0.0f);
        uint2 pp;
        pp.x = pkbf(v0, v1);
        pp.y = pkbf(v2, v3);
        *(uint2*)&g_hb[slot][n] = pp;
    }
}

// ---------------- K4: HMMA bf16 GEMM 512 -> 12288 + bias + sigmoid ---------
// CTA 128x128, 8 warps (4M x 2N), K-chunks of 32, 3-stage cp.async pipeline,
// 2 CTAs per SM for latency hiding.
#define ASTB 10240          // bytes per A stage (128 rows x 80 B)
#define BSTB 8704           // bytes per B stage (32 rows x 272 B)
#define NSTG 3
#define GEMM_DSMEM (NSTG * (ASTB + BSTB))   // 56832

__device__ __forceinline__ void ldsm4(uint32_t* r, uint32_t addr) {
    asm volatile("ldmatrix.sync.aligned.m8n8.x4.shared.b16 {%0,%1,%2,%3}, [%4];"
                 : "=r"(r[0]), "=r"(r[1]), "=r"(r[2]), "=r"(r[3]) : "r"(addr));
}
__device__ __forceinline__ void ldsm4t(uint32_t* r, uint32_t addr) {
    asm volatile("ldmatrix.sync.aligned.m8n8.x4.trans.shared.b16 {%0,%1,%2,%3}, [%4];"
                 : "=r"(r[0]), "=r"(r[1]), "=r"(r[2]), "=r"(r[3]) : "r"(addr));
}
__device__ __forceinline__ void mma16816(float* d, const uint32_t* a,
                                         uint32_t b0, uint32_t b1) {
    asm volatile("mma.sync.aligned.m16n8k16.row.col.f32.bf16.bf16.f32 "
                 "{%0,%1,%2,%3}, {%4,%5,%6,%7}, {%8,%9}, {%0,%1,%2,%3};"
                 : "+f"(d[0]), "+f"(d[1]), "+f"(d[2]), "+f"(d[3])
                 : "r"(a[0]), "r"(a[1]), "r"(a[2]), "r"(a[3]), "r"(b0), "r"(b1));
}

__global__ __launch_bounds__(256, 2) void k_gemm_mma(const float* __restrict__ b2) {
    int nrows = g_nrows;
    int mbase = blockIdx.y * 128;
    if (mbase >= nrows) return;
    int n0 = blockIdx.x * 128;

    extern __shared__ __align__(16) char dsm[];
    uint32_t smBase = smem_u32(dsm);

    int t = threadIdx.x, wid = t >> 5, lane = t & 31;
    int warpM = wid & 3, warpN = wid >> 2;

    float acc[2][8][4];
#pragma unroll
    for (int mi = 0; mi < 2; mi++)
#pragma unroll
        for (int n8 = 0; n8 < 8; n8++)
#pragma unroll
            for (int r = 0; r < 4; r++) acc[mi][n8][r] = 0.0f;

    // per-thread cp.async slot indices
    int mA0 = t >> 2,        kqA0 = t & 3;
    int mA1 = (t + 256) >> 2, kqA1 = (t + 256) & 3;
    int kB0 = t >> 4,        cB0 = t & 15;
    int kB1 = (t + 256) >> 4, cB1 = (t + 256) & 15;

#define ISSUE_CHUNK(c, st) do {                                                \
    int _k0 = (c) * 32;                                                        \
    uint32_t _aB = smBase + (st) * ASTB;                                       \
    uint32_t _bB = smBase + NSTG * ASTB + (st) * BSTB;                         \
    cpasync16(_aB + mA0 * 80 + kqA0 * 16, &g_hb[mbase + mA0][_k0 + kqA0 * 8]); \
    cpasync16(_aB + mA1 * 80 + kqA1 * 16, &g_hb[mbase + mA1][_k0 + kqA1 * 8]); \
    cpasync16(_bB + kB0 * 272 + cB0 * 16,                                      \
              &g_W2b[(size_t)(_k0 + kB0) * NOUT + n0 + cB0 * 8]);              \
    cpasync16(_bB + kB1 * 272 + cB1 * 16,                                      \
              &g_W2b[(size_t)(_k0 + kB1) * NOUT + n0 + cB1 * 8]);              \
    CP_COMMIT();                                                               \
} while (0)

    ISSUE_CHUNK(0, 0);
    ISSUE_CHUNK(1, 1);

    for (int c = 0; c < 16; c++) {
        int st = c % 3;
        if (c < 14) CP_WAIT(1);      // chunk c landed (c+1 may be in flight)
        else        CP_WAIT(0);
        __syncthreads();             // all warps done consuming stage (c-1)%3
        if (c < 14) ISSUE_CHUNK(c + 2, (c + 2) % 3);

        uint32_t aB = smBase + st * ASTB;
        uint32_t bB = smBase + NSTG * ASTB + st * BSTB;

        // hoist all A frags for this chunk (both ks, both mi)
        uint32_t afr[2][2][4];
#pragma unroll
        for (int ks = 0; ks < 2; ks++)
#pragma unroll
            for (int mi = 0; mi < 2; mi++) {
                int row = warpM * 32 + mi * 16 + (lane & 15);
                ldsm4(afr[ks][mi], aB + row * 80 + ks * 32 + (lane >> 4) * 16);
            }
#pragma unroll
        for (int ks = 0; ks < 2; ks++) {
#pragma unroll
            for (int nt = 0; nt < 4; nt++) {
                uint32_t bfr[4];
                int krow = ks * 16 + (lane & 15);
                ldsm4t(bfr, bB + krow * 272 + (warpN * 64 + nt * 16) * 2 + (lane >> 4) * 16);
#pragma unroll
                for (int mi = 0; mi < 2; mi++) {
                    mma16816(acc[mi][nt * 2 + 0], afr[ks][mi], bfr[0], bfr[1]);
                    mma16816(acc[mi][nt * 2 + 1], afr[ks][mi], bfr[2], bfr[3]);
                }
            }
        }
    }

    // ---- epilogue: bias + sigmoid, store via d-frag mapping
    int p = lane >> 2, q = lane & 3;
#pragma unroll
    for (int mi = 0; mi < 2; mi++) {
#pragma unroll
        for (int half = 0; half < 2; half++) {
            int slot = mbase + warpM * 32 + mi * 16 + p + half * 8;
            if (slot < nrows) {
                int row = g_rows[slot];
#pragma unroll
                for (int n8 = 0; n8 < 8; n8++) {
                    int col = n0 + warpN * 64 + n8 * 8 + q * 2;
                    float2 bb = *(const float2*)&b2[col];
                    float v0 = acc[mi][n8][half * 2 + 0] + bb.x;
                    float v1 = acc[mi][n8][half * 2 + 1] + bb.y;
                    float2 o;
                    o.x = 1.0f / (1.0f + __expf(-v0));
                    o.y = 1.0f / (1.0f + __expf(-v1));
                    *(float2*)&g_dec[row][col] = o;
                }
            }
        }
    }
}

// ---------------- K5: final bilinear sample + composite --------------------
__global__ void k_sample(float* __restrict__ out) {
    int id = blockIdx.x * 256 + threadIdx.x;
    int b = id >> 14;
    int y = (id >> 7) & 127;
    int x = id & 127;
    int s = g_winner[b][y][x];

    float val[3] = {0.0f, 0.0f, 0.0f};
    if (s >= 0) {
        float4 p = g_candf[b][s];
        int dec = g_candd[b][s];
        float gx = -1.0f + x * (2.0f / 127.0f);
        float gy = -1.0f + y * (2.0f / 127.0f);
        float u = (gx - p.x) * p.z;
        float v = (gy - p.y) * p.w;
        float px = (u + 1.0f) * 0.5f * 63.0f;
        float py = (v + 1.0f) * 0.5f * 63.0f;
        float x0 = floorf(px), y0 = floorf(py);
        float wx = px - x0, wy = py - y0;
        int xi = (int)x0, yi = (int)y0;
        bool vx0 = (xi >= 0) && (xi < OBJW);
        bool vx1 = (xi + 1 >= 0) && (xi + 1 < OBJW);
        bool vy0 = (yi >= 0) && (yi < OBJW);
        bool vy1 = (yi + 1 >= 0) && (yi + 1 < OBJW);
        float w00 = (vy0 && vx0) ? (1.0f - wy) * (1.0f - wx) : 0.0f;
        float w01 = (vy0 && vx1) ? (1.0f - wy) * wx : 0.0f;
        float w10 = (vy1 && vx0) ? wy * (1.0f - wx) : 0.0f;
        float w11 = (vy1 && vx1) ? wy * wx : 0.0f;
        int xc0 = min(max(xi, 0), 63),     xc1 = min(max(xi + 1, 0), 63);
        int yc0 = min(max(yi, 0), 63),     yc1 = min(max(yi + 1, 0), 63);
        const float* base = g_dec[b * NOBJ + dec];
#pragma unroll
        for (int c = 0; c < 3; c++) {
            const float* im = base + c * (OBJW * OBJW);
            val[c] = im[yc0 * OBJW + xc0] * w00 + im[yc0 * OBJW + xc1] * w01 +
                     im[yc1 * OBJW + xc0] * w10 + im[yc1 * OBJW + xc1] * w11;
        }
    }
#pragma unroll
    for (int c = 0; c < 3; c++)
        out[(((size_t)b * 3 + c) * IMGW + y) * IMGW + x] = val[c];
}

// ---------------------------------------------------------------------------
extern "C" void kernel_launch(void* const* d_in, const int* in_sizes, int n_in,
                              void* d_out, int out_size) {
    const float* z_what    = (const float*)d_in[0];
    const float* z_where   = (const float*)d_in[1];
    const float* z_depth   = (const float*)d_in[2];
    const float* W1        = (const float*)d_in[3];
    const float* b1        = (const float*)d_in[4];
    const float* W2        = (const float*)d_in[5];
    const float* b2        = (const float*)d_in[6];
    const int*   z_present = (const int*)d_in[7];
    float* out = (float*)d_out;

    static int attr_done = 0;
    if (!attr_done) {
        cudaFuncSetAttribute(k_gemm_mma,
                             cudaFuncAttributeMaxDynamicSharedMemorySize, GEMM_DSMEM);
        attr_done = 1;
    }

    k_sort<<<4 + 1024, 544>>>(z_depth, z_where, z_present, W2);
    k_winner<<<256, 256>>>();
    k_hidden<<<dim3(4, 34), 256>>>(z_what, W1, b1);
    k_gemm_mma<<<dim3(96, 5), 256, GEMM_DSMEM>>>(b2);
    k_sample<<<256, 256>>>(out);
}

// round 10
// speedup vs baseline: 1.8475x; 1.0506x over previous
#include <cuda_runtime.h>
#include <cuda_bf16.h>
#include <cstdint>
#include <math.h>

#define NB    4
#define NOBJ  135
#define NFEAT 540
#define ZD    64
#define HID   512
#define NOUT  12288   // 3*64*64
#define IMGW  128
#define OBJW  64

// ================= scratch (device globals; no allocation allowed) =========
__device__ float4        g_candf[NB][NFEAT];   // ax, ay, 1/w, 1/h
__device__ int           g_candd[NB][NFEAT];
__device__ int           g_ncand[NB];
__device__ int           g_need[NB][NOBJ];
__device__ int           g_rows[640];
__device__ int           g_nrows;
__device__ __align__(16) __nv_bfloat16 g_hb[640][HID];    // hidden acts, bf16
__device__ __align__(16) __nv_bfloat16 g_W2b[HID * NOUT]; // W2 in bf16
__device__ __align__(16) float g_dec[NB*NOBJ][NOUT];
__device__ int           g_winner[NB][IMGW][IMGW];

__device__ __forceinline__ int recon_idx(int j) {
    if (j < 400) return j >> 2;
    if (j < 500) return 100 + ((j - 400) >> 2);
    if (j < 536) return 125 + ((j - 500) >> 2);
    return 134;
}
__device__ __forceinline__ uint32_t smem_u32(const void* p) {
    uint32_t a;
    asm("{ .reg .u64 t; cvta.to.shared.u64 t, %1; cvt.u32.u64 %0, t; }" : "=r"(a) : "l"(p));
    return a;
}
__device__ __forceinline__ uint32_t pkbf(float a, float b) {
    __nv_bfloat162 h = __floats2bfloat162_rn(a, b);
    return *(uint32_t*)&h;
}
__device__ __forceinline__ void cpasync16(uint32_t saddr, const void* g) {
    asm volatile("cp.async.cg.shared.global [%0], [%1], 16;" :: "r"(saddr), "l"(g));
}
#define CP_COMMIT() asm volatile("cp.async.commit_group;" ::: "memory")
#define CP_WAIT(N)  asm volatile("cp.async.wait_group %0;" :: "n"(N) : "memory")

// ---------------- K1: sort/candidates (blocks 0-3) + W2->bf16 (blocks 4+) --
__global__ void k_sort(const float* __restrict__ zdepth,
                       const float* __restrict__ zwhere,
                       const int*   __restrict__ zpres,
                       const float* __restrict__ W2) {
    int t = threadIdx.x;   // 544

    if (blockIdx.x >= 4) {
        // W2 fp32 -> bf16 conversion, grid-stride over uint4 outputs
        int cid = (blockIdx.x - 4) * blockDim.x + t;
        const float4* src = (const float4*)W2;
        uint4* dst = (uint4*)g_W2b;
        for (int o = cid; o < (HID * NOUT) / 8; o += 1024 * 544) {
            float4 f0 = src[o * 2], f1 = src[o * 2 + 1];
            uint4 v;
            v.x = pkbf(f0.x, f0.y);
            v.y = pkbf(f0.z, f0.w);
            v.z = pkbf(f1.x, f1.y);
            v.w = pkbf(f1.z, f1.w);
            dst[o] = v;
        }
        return;
    }

    int b = blockIdx.x;
    __shared__ float sd[NFEAT];
    __shared__ int   sord[NFEAT];
    __shared__ int   swsum[17];

    if (b == 0 && t == 0) g_nrows = 0;
    if (t < NFEAT) sd[t] = zdepth[b * NOBJ + recon_idx(t)];
    if (t < NOBJ)  g_need[b][t] = 0;
    __syncthreads();

    if (t < NFEAT) {
        float dj = sd[t];
        int r = 0;
        for (int k = 0; k < NFEAT; k++) {
            float dk = sd[k];
            r += (dk > dj) || (dk == dj && k < t);   // stable, descending
        }
        sord[r] = t;
    }
    __syncthreads();

    int j    = (t < NFEAT) ? sord[t] : -1;
    int flag = (t < NFEAT) ? (zpres[b * NFEAT + j] != 0) : 0;
    unsigned bal = __ballot_sync(0xffffffffu, flag);
    int lane = t & 31, w = t >> 5;
    if (lane == 0) swsum[w] = __popc(bal);
    __syncthreads();
    int base = 0;
    for (int i = 0; i < w; i++) base += swsum[i];
    if (flag) {
        int pos = base + __popc(bal & ((1u << lane) - 1u));
        const float* zw = zwhere + (size_t)(b * NFEAT + j) * 4;
        float cx = zw[0], cy = zw[1], ww = zw[2], hh = zw[3];
        ww = fmaxf(ww, 0.01f);
        hh = fmaxf(hh, 0.01f);
        float4 f;
        f.x = 2.0f * cx - 1.0f;
        f.y = 2.0f * cy - 1.0f;
        f.z = 1.0f / ww;               // reciprocal: winner/sample use FMUL
        f.w = 1.0f / hh;
        g_candf[b][pos] = f;
        g_candd[b][pos] = recon_idx(j);
    }
    if (t == 0) {
        int s = 0;
        for (int i = 0; i < 17; i++) s += swsum[i];
        g_ncand[b] = s;
    }
}

// ---------------- K2: per-pixel winner + inline need-compaction ------------
__global__ void k_winner() {
    int blk = blockIdx.x;
    int b = blk >> 6;
    int ypair = blk & 63;
    int t = threadIdx.x;
    int y = ypair * 2 + (t >> 7);
    int x = t & 127;

    __shared__ float4 cf[NFEAT];
    __shared__ int    cd[NFEAT];
    int nc = g_ncand[b];
    for (int i = t; i < nc; i += 256) { cf[i] = g_candf[b][i]; cd[i] = g_candd[b][i]; }
    __syncthreads();

    float gx = -1.0f + x * (2.0f / 127.0f);
    float gy = -1.0f + y * (2.0f / 127.0f);

    int win = -1;
    for (int s = 0; s < nc; s++) {
        float4 p = cf[s];
        float u = (gx - p.x) * p.z;
        float v = (gy - p.y) * p.w;
        float px = (u + 1.0f) * 0.5f * 63.0f;
        float py = (v + 1.0f) * 0.5f * 63.0f;
        float x0 = floorf(px), y0 = floorf(py);
        float wx = px - x0, wy = py - y0;
        int xi = (int)x0, yi = (int)y0;
        bool vx0 = (xi >= 0) && (xi < OBJW);
        bool vx1 = (xi + 1 >= 0) && (xi + 1 < OBJW);
        bool vy0 = (yi >= 0) && (yi < OBJW);
        bool vy1 = (yi + 1 >= 0) && (yi + 1 < OBJW);
        bool wxp = wx > 0.0f, wyp = wy > 0.0f;
        bool cov = (vy0 && vx0) || (vy0 && vx1 && wxp) ||
                   (vy1 && vx0 && wyp) || (vy1 && vx1 && wxp && wyp);
        if (cov) {
            win = s;
            int d = cd[s];
            if (g_need[b][d] == 0) {
                if (atomicExch(&g_need[b][d], 1) == 0) {
                    int slot = atomicAdd(&g_nrows, 1);
                    g_rows[slot] = b * NOBJ + d;
                }
            }
            break;
        }
    }
    g_winner[b][y][x] = win;
}

// ---------------- K3: hidden layer 64->512 relu, tiled, bf16 out -----------
__global__ __launch_bounds__(256) void k_hidden(const float* __restrict__ zwhat,
                                                const float* __restrict__ W1,
                                                const float* __restrict__ b1) {
    __shared__ __align__(16) float sA[16][68];   // row stride 272 B (16-aligned)
    __shared__ __align__(16) float sW[64][132];
    int nt = blockIdx.x, mt = blockIdx.y;    // 4 x 34
    int nrows = g_nrows;
    int t = threadIdx.x;

    {   // A tile 16x64 = 256 float4
        int m = t >> 4, k4 = t & 15;
        int slot = mt * 16 + m;
        float4 v = make_float4(0.f, 0.f, 0.f, 0.f);
        if (slot < nrows) v = *(const float4*)&zwhat[(size_t)g_rows[slot] * ZD + k4 * 4];
        *(float4*)&sA[m][k4 * 4] = v;
    }
#pragma unroll
    for (int l = 0; l < 8; l++) {
        int id = t + l * 256;           // W tile 64x128 (2048 float4)
        int k = id >> 5, c4 = id & 31;
        float4 v = *(const float4*)&W1[(size_t)k * HID + nt * 128 + c4 * 4];
        *(float4*)&sW[k][c4 * 4] = v;
    }
    __syncthreads();

    int tm = t >> 5, tn = t & 31;       // rows tm*2.., cols tn*4..
    float acc[2][4];
#pragma unroll
    for (int i = 0; i < 2; i++)
#pragma unroll
        for (int j = 0; j < 4; j++) acc[i][j] = 0.0f;

#pragma unroll 8
    for (int k = 0; k < 64; k++) {
        float a[2], w[4];
#pragma unroll
        for (int i = 0; i < 2; i++) a[i] = sA[tm * 2 + i][k];
#pragma unroll
        for (int j = 0; j < 4; j++) w[j] = sW[k][tn * 4 + j];
#pragma unroll
        for (int i = 0; i < 2; i++)
#pragma unroll
            for (int j = 0; j < 4; j++) acc[i][j] = fmaf(a[i], w[j], acc[i][j]);
    }

#pragma unroll
    for (int i = 0; i < 2; i++) {
        int slot = mt * 16 + tm * 2 + i;
        int n = nt * 128 + tn * 4;
        float v0 = fmaxf(acc[i][0] + b1[n + 0], 0.0f);
        float v1 = fmaxf(acc[i][1] + b1[n + 1], 0.0f);
        float v2 = fmaxf(acc[i][2] + b1[n + 2], 0.0f);
        float v3 = fmaxf(acc[i][3] + b1[n + 3], 0.0f);
        uint2 pp;
        pp.x = pkbf(v0, v1);
        pp.y = pkbf(v2, v3);
        *(uint2*)&g_hb[slot][n] = pp;
    }
}

// ---------------- K4: HMMA bf16 GEMM 512 -> 12288 + bias + sigmoid ---------
// CTA 128x128, 16 warps (4M x 4N, warp tile 32x32), K-chunks of 32,
// 3-stage cp.async pipeline. One big CTA -> 16 resident warps/SM.
#define ASTB 10240          // bytes per A stage (128 rows x 80 B)
#define BSTB 8704           // bytes per B stage (32 rows x 272 B)
#define NSTG 3
#define GEMM_DSMEM (NSTG * (ASTB + BSTB))   // 56832

__device__ __forceinline__ void ldsm4(uint32_t* r, uint32_t addr) {
    asm volatile("ldmatrix.sync.aligned.m8n8.x4.shared.b16 {%0,%1,%2,%3}, [%4];"
                 : "=r"(r[0]), "=r"(r[1]), "=r"(r[2]), "=r"(r[3]) : "r"(addr));
}
__device__ __forceinline__ void ldsm4t(uint32_t* r, uint32_t addr) {
    asm volatile("ldmatrix.sync.aligned.m8n8.x4.trans.shared.b16 {%0,%1,%2,%3}, [%4];"
                 : "=r"(r[0]), "=r"(r[1]), "=r"(r[2]), "=r"(r[3]) : "r"(addr));
}
__device__ __forceinline__ void mma16816(float* d, const uint32_t* a,
                                         uint32_t b0, uint32_t b1) {
    asm volatile("mma.sync.aligned.m16n8k16.row.col.f32.bf16.bf16.f32 "
                 "{%0,%1,%2,%3}, {%4,%5,%6,%7}, {%8,%9}, {%0,%1,%2,%3};"
                 : "+f"(d[0]), "+f"(d[1]), "+f"(d[2]), "+f"(d[3])
                 : "r"(a[0]), "r"(a[1]), "r"(a[2]), "r"(a[3]), "r"(b0), "r"(b1));
}

__global__ __launch_bounds__(512, 1) void k_gemm_mma(const float* __restrict__ b2) {
    int nrows = g_nrows;
    int mbase = blockIdx.y * 128;
    if (mbase >= nrows) return;
    int n0 = blockIdx.x * 128;

    extern __shared__ __align__(16) char dsm[];
    uint32_t smBase = smem_u32(dsm);

    int t = threadIdx.x, wid = t >> 5, lane = t & 31;
    int warpM = wid & 3, warpN = wid >> 2;      // 4 x 4, warp tile 32x32

    float acc[2][4][4];                          // [mi][cg*2+n8][r]
#pragma unroll
    for (int mi = 0; mi < 2; mi++)
#pragma unroll
        for (int n8 = 0; n8 < 4; n8++)
#pragma unroll
            for (int r = 0; r < 4; r++) acc[mi][n8][r] = 0.0f;

    // per-thread cp.async slots: exactly one 16B A unit + one 16B B unit
    int mA = t >> 2,  kqA = t & 3;               // A: 128 rows x 4 units
    int kB = t >> 4,  cB  = t & 15;              // B: 32 rows x 16 units

#define ISSUE_CHUNK(c, st) do {                                                \
    int _k0 = (c) * 32;                                                        \
    uint32_t _aB = smBase + (st) * ASTB;                                       \
    uint32_t _bB = smBase + NSTG * ASTB + (st) * BSTB;                         \
    cpasync16(_aB + mA * 80 + kqA * 16, &g_hb[mbase + mA][_k0 + kqA * 8]);     \
    cpasync16(_bB + kB * 272 + cB * 16,                                        \
              &g_W2b[(size_t)(_k0 + kB) * NOUT + n0 + cB * 8]);                \
    CP_COMMIT();                                                               \
} while (0)

    ISSUE_CHUNK(0, 0);
    ISSUE_CHUNK(1, 1);

    for (int c = 0; c < 16; c++) {
        int st = c % 3;
        if (c < 14) CP_WAIT(1);      // chunk c landed (c+1 may be in flight)
        else        CP_WAIT(0);
        __syncthreads();             // all warps done consuming stage (c-1)%3
        if (c < 14) ISSUE_CHUNK(c + 2, (c + 2) % 3);

        uint32_t aB = smBase + st * ASTB;
        uint32_t bB = smBase + NSTG * ASTB + st * BSTB;

        // hoist A frags for this chunk (both ks, both mi halves)
        uint32_t afr[2][2][4];
#pragma unroll
        for (int ks = 0; ks < 2; ks++)
#pragma unroll
            for (int mi = 0; mi < 2; mi++) {
                int row = warpM * 32 + mi * 16 + (lane & 15);
                ldsm4(afr[ks][mi], aB + row * 80 + ks * 32 + (lane >> 4) * 16);
            }
#pragma unroll
        for (int ks = 0; ks < 2; ks++) {
#pragma unroll
            for (int cg = 0; cg < 2; cg++) {     // two 16-col groups
                uint32_t bfr[4];
                int krow = ks * 16 + (lane & 15);
                ldsm4t(bfr, bB + krow * 272 + (warpN * 32 + cg * 16) * 2 + (lane >> 4) * 16);
#pragma unroll
                for (int mi = 0; mi < 2; mi++) {
                    mma16816(acc[mi][cg * 2 + 0], afr[ks][mi], bfr[0], bfr[1]);
                    mma16816(acc[mi][cg * 2 + 1], afr[ks][mi], bfr[2], bfr[3]);
                }
            }
        }
    }

    // ---- epilogue: bias + sigmoid, store via d-frag mapping
    int p = lane >> 2, q = lane & 3;
#pragma unroll
    for (int mi = 0; mi < 2; mi++) {
#pragma unroll
        for (int half = 0; half < 2; half++) {
            int slot = mbase + warpM * 32 + mi * 16 + p + half * 8;
            if (slot < nrows) {
                int row = g_rows[slot];
#pragma unroll
                for (int n8 = 0; n8 < 4; n8++) {
                    int col = n0 + warpN * 32 + n8 * 8 + q * 2;
                    float2 bb = *(const float2*)&b2[col];
                    float v0 = acc[mi][n8][half * 2 + 0] + bb.x;
                    float v1 = acc[mi][n8][half * 2 + 1] + bb.y;
                    float2 o;
                    o.x = 1.0f / (1.0f + __expf(-v0));
                    o.y = 1.0f / (1.0f + __expf(-v1));
                    *(float2*)&g_dec[row][col] = o;
                }
            }
        }
    }
}

// ---------------- K5: final bilinear sample + composite --------------------
__global__ void k_sample(float* __restrict__ out) {
    int id = blockIdx.x * 256 + threadIdx.x;
    int b = id >> 14;
    int y = (id >> 7) & 127;
    int x = id & 127;
    int s = g_winner[b][y][x];

    float val[3] = {0.0f, 0.0f, 0.0f};
    if (s >= 0) {
        float4 p = g_candf[b][s];
        int dec = g_candd[b][s];
        float gx = -1.0f + x * (2.0f / 127.0f);
        float gy = -1.0f + y * (2.0f / 127.0f);
        float u = (gx - p.x) * p.z;
        float v = (gy - p.y) * p.w;
        float px = (u + 1.0f) * 0.5f * 63.0f;
        float py = (v + 1.0f) * 0.5f * 63.0f;
        float x0 = floorf(px), y0 = floorf(py);
        float wx = px - x0, wy = py - y0;
        int xi = (int)x0, yi = (int)y0;
        bool vx0 = (xi >= 0) && (xi < OBJW);
        bool vx1 = (xi + 1 >= 0) && (xi + 1 < OBJW);
        bool vy0 = (yi >= 0) && (yi < OBJW);
        bool vy1 = (yi + 1 >= 0) && (yi + 1 < OBJW);
        float w00 = (vy0 && vx0) ? (1.0f - wy) * (1.0f - wx) : 0.0f;
        float w01 = (vy0 && vx1) ? (1.0f - wy) * wx : 0.0f;
        float w10 = (vy1 && vx0) ? wy * (1.0f - wx) : 0.0f;
        float w11 = (vy1 && vx1) ? wy * wx : 0.0f;
        int xc0 = min(max(xi, 0), 63),     xc1 = min(max(xi + 1, 0), 63);
        int yc0 = min(max(yi, 0), 63),     yc1 = min(max(yi + 1, 0), 63);
        const float* base = g_dec[b * NOBJ + dec];
#pragma unroll
        for (int c = 0; c < 3; c++) {
            const float* im = base + c * (OBJW * OBJW);
            val[c] = im[yc0 * OBJW + xc0] * w00 + im[yc0 * OBJW + xc1] * w01 +
                     im[yc1 * OBJW + xc0] * w10 + im[yc1 * OBJW + xc1] * w11;
        }
    }
#pragma unroll
    for (int c = 0; c < 3; c++)
        out[(((size_t)b * 3 + c) * IMGW + y) * IMGW + x] = val[c];
}

// ---------------------------------------------------------------------------
extern "C" void kernel_launch(void* const* d_in, const int* in_sizes, int n_in,
                              void* d_out, int out_size) {
    const float* z_what    = (const float*)d_in[0];
    const float* z_where   = (const float*)d_in[1];
    const float* z_depth   = (const float*)d_in[2];
    const float* W1        = (const float*)d_in[3];
    const float* b1        = (const float*)d_in[4];
    const float* W2        = (const float*)d_in[5];
    const float* b2        = (const float*)d_in[6];
    const int*   z_present = (const int*)d_in[7];
    float* out = (float*)d_out;

    static int attr_done = 0;
    if (!attr_done) {
        cudaFuncSetAttribute(k_gemm_mma,
                             cudaFuncAttributeMaxDynamicSharedMemorySize, GEMM_DSMEM);
        attr_done = 1;
    }

    k_sort<<<4 + 1024, 544>>>(z_depth, z_where, z_present, W2);
    k_winner<<<256, 256>>>();
    k_hidden<<<dim3(4, 34), 256>>>(z_what, W1, b1);
    k_gemm_mma<<<dim3(96, 5), 512, GEMM_DSMEM>>>(b2);
    k_sample<<<256, 256>>>(out);
}